// round 11
// baseline (speedup 1.0000x reference)
#include <cuda_runtime.h>
#include <cuda_bf16.h>
#include <stdint.h>

// ---------------------------------------------------------------------------
// LlamaAttention: S=2048, HID=4096, NH=32, NKV=8, D=128
// Projections: int8 dual-level (x ~ s*(a1 + a2/254)) via mma.sync m16n8k32
//   (3 IMMA products, s32 accum, fp32 epilogue) -> ~1e-4 accuracy.
// Attention: bf16x3 warp-MMA flash (unchanged). RoPE fused in QKV epilogue.
// tcgen05 unavailable (PTX target compute_103).
// ---------------------------------------------------------------------------

#define S_LEN 2048
#define HID   4096
#define NH    32
#define NKV   8
#define HD    128
#define KVDIM (NKV * HD)   // 1024
#define KDIM  4096

// fp32 scratch
__device__ float g_v[S_LEN * KVDIM];
__device__ float g_attn[S_LEN * HID];

// int8 quantized operands (a1 = level1, a2 = level2 residual*254)
__device__ uint8_t g_hq1[S_LEN * KDIM],  g_hq2[S_LEN * KDIM];
__device__ uint8_t g_wqq1[HID * KDIM],   g_wqq2[HID * KDIM];
__device__ uint8_t g_wkq1[KVDIM * KDIM], g_wkq2[KVDIM * KDIM];
__device__ uint8_t g_wvq1[KVDIM * KDIM], g_wvq2[KVDIM * KDIM];
__device__ uint8_t g_woq1[HID * KDIM],   g_woq2[HID * KDIM];
__device__ uint8_t g_atq1[S_LEN * KDIM], g_atq2[S_LEN * KDIM];
__device__ float g_s_hid[S_LEN], g_s_wq[HID], g_s_wk[KVDIM], g_s_wv[KVDIM];
__device__ float g_s_wo[HID], g_s_at[S_LEN];

// bf16 attention operands
__device__ __nv_bfloat16 g_qr_hi[S_LEN * HID];
__device__ __nv_bfloat16 g_qr_lo[S_LEN * HID];
__device__ __nv_bfloat16 g_kr_hi[S_LEN * KVDIM];
__device__ __nv_bfloat16 g_kr_lo[S_LEN * KVDIM];
__device__ __nv_bfloat16 g_vt_hi[KVDIM * S_LEN];
__device__ __nv_bfloat16 g_vt_lo[KVDIM * S_LEN];

__device__ __forceinline__ uint32_t pack_hl(float f0, float f1, uint32_t& lo) {
    __nv_bfloat162 h = __floats2bfloat162_rn(f0, f1);
    float r0 = f0 - __bfloat162float(h.x);
    float r1 = f1 - __bfloat162float(h.y);
    __nv_bfloat162 l = __floats2bfloat162_rn(r0, r1);
    lo = *(uint32_t*)&l;
    return *(uint32_t*)&h;
}

// ---------------------------------------------------------------------------
// Row quantization: one 256-thread block per 4096-float row.
// ---------------------------------------------------------------------------
__device__ __forceinline__ void quant_row_fn(const float* __restrict__ src,
                                             uint8_t* __restrict__ q1,
                                             uint8_t* __restrict__ q2,
                                             float* __restrict__ sc) {
    __shared__ float wmx[8];
    const int tid = threadIdx.x;
    const int lane = tid & 31;
    const int w = tid >> 5;
    float4 f[4];
#pragma unroll
    for (int j = 0; j < 4; j++) f[j] = *(const float4*)(src + tid * 16 + j * 4);
    float mx = 0.f;
#pragma unroll
    for (int j = 0; j < 4; j++) {
        mx = fmaxf(mx, fmaxf(fmaxf(fabsf(f[j].x), fabsf(f[j].y)),
                             fmaxf(fabsf(f[j].z), fabsf(f[j].w))));
    }
#pragma unroll
    for (int off = 16; off >= 1; off >>= 1)
        mx = fmaxf(mx, __shfl_xor_sync(0xffffffffu, mx, off));
    if (lane == 0) wmx[w] = mx;
    __syncthreads();
    if (tid == 0) {
        float m = wmx[0];
#pragma unroll
        for (int i = 1; i < 8; i++) m = fmaxf(m, wmx[i]);
        m = fmaxf(m, 1e-30f);
        wmx[0] = m;
        *sc = m * (1.0f / 127.0f);
    }
    __syncthreads();
    const float invs = 127.0f / wmx[0];
#pragma unroll
    for (int j = 0; j < 4; j++) {
        uint32_t w1 = 0, w2 = 0;
        const float vals[4] = {f[j].x, f[j].y, f[j].z, f[j].w};
#pragma unroll
        for (int e = 0; e < 4; e++) {
            float y = vals[e] * invs;
            int a1 = __float2int_rn(y);
            a1 = max(-127, min(127, a1));
            float r = y - (float)a1;
            int a2 = __float2int_rn(r * 254.0f);
            a2 = max(-127, min(127, a2));
            w1 |= ((uint32_t)(uint8_t)(int8_t)a1) << (e * 8);
            w2 |= ((uint32_t)(uint8_t)(int8_t)a2) << (e * 8);
        }
        ((uint32_t*)q1)[tid * 4 + j] = w1;
        ((uint32_t*)q2)[tid * 4 + j] = w2;
    }
}

__global__ void quant_all(const float* __restrict__ hidden,
                          const float* __restrict__ wq,
                          const float* __restrict__ wk,
                          const float* __restrict__ wv,
                          const float* __restrict__ wo) {
    int row = blockIdx.x;
    if (row < 2048) {
        quant_row_fn(hidden + (size_t)row * KDIM, g_hq1 + (size_t)row * KDIM,
                     g_hq2 + (size_t)row * KDIM, g_s_hid + row);
    } else if (row < 6144) {
        int r = row - 2048;
        quant_row_fn(wq + (size_t)r * KDIM, g_wqq1 + (size_t)r * KDIM,
                     g_wqq2 + (size_t)r * KDIM, g_s_wq + r);
    } else if (row < 7168) {
        int r = row - 6144;
        quant_row_fn(wk + (size_t)r * KDIM, g_wkq1 + (size_t)r * KDIM,
                     g_wkq2 + (size_t)r * KDIM, g_s_wk + r);
    } else if (row < 8192) {
        int r = row - 7168;
        quant_row_fn(wv + (size_t)r * KDIM, g_wvq1 + (size_t)r * KDIM,
                     g_wvq2 + (size_t)r * KDIM, g_s_wv + r);
    } else {
        int r = row - 8192;
        quant_row_fn(wo + (size_t)r * KDIM, g_woq1 + (size_t)r * KDIM,
                     g_woq2 + (size_t)r * KDIM, g_s_wo + r);
    }
}

__global__ void quant_attn() {
    int row = blockIdx.x;
    quant_row_fn(g_attn + (size_t)row * KDIM, g_atq1 + (size_t)row * KDIM,
                 g_atq2 + (size_t)row * KDIM, g_s_at + row);
}

// ---------------------------------------------------------------------------
// warp-MMA primitives
// ---------------------------------------------------------------------------
__device__ __forceinline__ void ldsm_x4(uint32_t addr, uint32_t& r0, uint32_t& r1,
                                        uint32_t& r2, uint32_t& r3) {
    asm volatile("ldmatrix.sync.aligned.m8n8.x4.shared.b16 {%0,%1,%2,%3}, [%4];"
                 : "=r"(r0), "=r"(r1), "=r"(r2), "=r"(r3) : "r"(addr));
}

__device__ __forceinline__ void mma_bf16(float* c, const uint32_t* a, const uint32_t* b) {
    asm volatile(
        "mma.sync.aligned.m16n8k16.row.col.f32.bf16.bf16.f32 "
        "{%0,%1,%2,%3},{%4,%5,%6,%7},{%8,%9},{%0,%1,%2,%3};"
        : "+f"(c[0]), "+f"(c[1]), "+f"(c[2]), "+f"(c[3])
        : "r"(a[0]), "r"(a[1]), "r"(a[2]), "r"(a[3]), "r"(b[0]), "r"(b[1]));
}

__device__ __forceinline__ void mma_s8(int* c, const uint32_t* a, const uint32_t* b) {
    asm volatile(
        "mma.sync.aligned.m16n8k32.row.col.s32.s8.s8.s32 "
        "{%0,%1,%2,%3},{%4,%5,%6,%7},{%8,%9},{%0,%1,%2,%3};"
        : "+r"(c[0]), "+r"(c[1]), "+r"(c[2]), "+r"(c[3])
        : "r"(a[0]), "r"(a[1]), "r"(a[2]), "r"(a[3]), "r"(b[0]), "r"(b[1]));
}

// ---------------------------------------------------------------------------
// int8 dual-level GEMM: C = sA*sB*(A1·B1 + (A1·B2 + A2·B1)/254)
// Block 128x128, warp tile 32x64, K-block 64 (2 k32 steps), 256 threads,
// 2-stage cp.async, 80B-padded rows.
// ---------------------------------------------------------------------------
#define ILDT  80
#define ITILE (128 * ILDT)               // 10240
#define ISTG  (4 * ITILE)                // A1,A2,B1,B2 = 40960
#define ISMEM (2 * ISTG)                 // 81920
#define INV254 (1.0f / 254.0f)

__device__ __forceinline__ void gemm_i8_body(
    const uint8_t* __restrict__ A1, const uint8_t* __restrict__ A2,
    const float* __restrict__ sA,
    const uint8_t* __restrict__ B1, const uint8_t* __restrict__ B2,
    const float* __restrict__ sB,
    float* __restrict__ Cf, __nv_bfloat16* __restrict__ Chi,
    __nv_bfloat16* __restrict__ Clo,
    const float* __restrict__ cosb, const float* __restrict__ sinb,
    int mode, int N, int bm, int bn, char* smem) {
    const int tid = threadIdx.x;
    const int lane = tid & 31;
    const int warp = tid >> 5;
    const int wr = warp >> 1;        // 0..3, 32-row slices
    const int wc = warp & 1;         // 0..1, 64-col slices
    uint32_t sbase = (uint32_t)__cvta_generic_to_shared(smem);

    int acc1[2][8][4], acc12[2][8][4];
#pragma unroll
    for (int mi = 0; mi < 2; mi++)
#pragma unroll
        for (int nf = 0; nf < 8; nf++)
#pragma unroll
            for (int t = 0; t < 4; t++) { acc1[mi][nf][t] = 0; acc12[mi][nf][t] = 0; }

    const uint8_t* mats[4] = {A1, A2, B1, B2};

    auto load_stage = [&](int s, int it) {
        const int kb = it * 64;
        uint32_t dst0 = sbase + s * ISTG;
#pragma unroll
        for (int i = 0; i < 8; i++) {
            int c = tid + i * 256;      // 0..2047
            int mat = c >> 9;           // 512 chunks per matrix
            int idx = c & 511;
            int row = idx >> 2;
            int ch = idx & 3;
            int grow = (mat < 2 ? bm : bn) + row;
            const void* gsrc = mats[mat] + (size_t)grow * KDIM + kb + ch * 16;
            uint32_t daddr = dst0 + mat * ITILE + row * ILDT + ch * 16;
            asm volatile("cp.async.cg.shared.global [%0], [%1], 16;"
                         :: "r"(daddr), "l"(gsrc));
        }
        asm volatile("cp.async.commit_group;");
    };

    const int NIT = KDIM / 64;   // 64
    load_stage(0, 0);
    load_stage(1, 1);

    const int brow = (lane & 7) + ((lane >> 4) << 3);
    const int bch = (lane >> 3) & 1;

    for (int it = 0; it < NIT; it++) {
        asm volatile("cp.async.wait_group 1;");
        __syncthreads();

        uint32_t sa = sbase + (it & 1) * ISTG;
#pragma unroll
        for (int ks = 0; ks < 2; ks++) {
            uint32_t af1[2][4], af2[2][4];
#pragma unroll
            for (int mi = 0; mi < 2; mi++) {
                uint32_t off = (uint32_t)((wr * 32 + mi * 16 + (lane & 15)) * ILDT +
                                          ks * 32 + (lane >> 4) * 16);
                ldsm_x4(sa + off, af1[mi][0], af1[mi][1], af1[mi][2], af1[mi][3]);
                ldsm_x4(sa + ITILE + off, af2[mi][0], af2[mi][1], af2[mi][2], af2[mi][3]);
            }
            uint32_t bf1[8][2], bf2[8][2];
#pragma unroll
            for (int ng = 0; ng < 4; ng++) {
                uint32_t off = (uint32_t)((wc * 64 + ng * 16 + brow) * ILDT +
                                          ks * 32 + bch * 16);
                uint32_t r0, r1, r2, r3;
                ldsm_x4(sa + 2 * ITILE + off, r0, r1, r2, r3);
                bf1[ng * 2][0] = r0; bf1[ng * 2][1] = r1;
                bf1[ng * 2 + 1][0] = r2; bf1[ng * 2 + 1][1] = r3;
                ldsm_x4(sa + 3 * ITILE + off, r0, r1, r2, r3);
                bf2[ng * 2][0] = r0; bf2[ng * 2][1] = r1;
                bf2[ng * 2 + 1][0] = r2; bf2[ng * 2 + 1][1] = r3;
            }
#pragma unroll
            for (int mi = 0; mi < 2; mi++)
#pragma unroll
                for (int nf = 0; nf < 8; nf++) {
                    mma_s8(acc1[mi][nf], af1[mi], bf1[nf]);
                    mma_s8(acc12[mi][nf], af1[mi], bf2[nf]);
                    mma_s8(acc12[mi][nf], af2[mi], bf1[nf]);
                }
        }
        __syncthreads();
        if (it + 2 < NIT) load_stage(it & 1, it + 2);
        else              asm volatile("cp.async.commit_group;");
    }

    // epilogue
#pragma unroll
    for (int mi = 0; mi < 2; mi++) {
        const int r0 = bm + wr * 32 + mi * 16 + (lane >> 2);
        const int r1 = r0 + 8;
        const float sa0 = sA[r0];
        const float sa1 = sA[r1];
#pragma unroll
        for (int nf = 0; nf < 8; nf++) {
            const int col = bn + wc * 64 + nf * 8 + (lane & 3) * 2;
            const float sb0 = sB[col];
            const float sb1 = sB[col + 1];
            float f00 = ((float)acc1[mi][nf][0] + (float)acc12[mi][nf][0] * INV254) * sa0 * sb0;
            float f01 = ((float)acc1[mi][nf][1] + (float)acc12[mi][nf][1] * INV254) * sa0 * sb1;
            float f10 = ((float)acc1[mi][nf][2] + (float)acc12[mi][nf][2] * INV254) * sa1 * sb0;
            float f11 = ((float)acc1[mi][nf][3] + (float)acc12[mi][nf][3] * INV254) * sa1 * sb1;
            if (mode == 0) {
                *(float2*)&Cf[(size_t)r0 * N + col] = make_float2(f00, f01);
                *(float2*)&Cf[(size_t)r1 * N + col] = make_float2(f10, f11);
            } else {
                const int i = (col & 127) >> 1;
                float c0 = cosb[r0 * 64 + i], s0 = sinb[r0 * 64 + i];
                float c1 = cosb[r1 * 64 + i], s1 = sinb[r1 * 64 + i];
                float x0 = f00 * c0 - f01 * s0, y0 = f00 * s0 + f01 * c0;
                float x1 = f10 * c1 - f11 * s1, y1 = f10 * s1 + f11 * c1;
                uint32_t lo32, hi32;
                hi32 = pack_hl(x0, y0, lo32);
                *(uint32_t*)&Chi[(size_t)r0 * N + col] = hi32;
                *(uint32_t*)&Clo[(size_t)r0 * N + col] = lo32;
                hi32 = pack_hl(x1, y1, lo32);
                *(uint32_t*)&Chi[(size_t)r1 * N + col] = hi32;
                *(uint32_t*)&Clo[(size_t)r1 * N + col] = lo32;
            }
        }
    }
}

// fused QKV: grid (16, 48). y<32: Q (RoPE); y<40: K (RoPE); else V (fp32).
__global__ __launch_bounds__(256, 1) void gemm_qkv_i8(const float* __restrict__ cosb,
                                                      const float* __restrict__ sinb) {
    extern __shared__ char smem[];
    const int y = blockIdx.y;
    const int bm = blockIdx.x * 128;
    if (y < 32) {
        gemm_i8_body(g_hq1, g_hq2, g_s_hid, g_wqq1, g_wqq2, g_s_wq,
                     nullptr, g_qr_hi, g_qr_lo, cosb, sinb, 1, HID,
                     bm, y * 128, smem);
    } else if (y < 40) {
        gemm_i8_body(g_hq1, g_hq2, g_s_hid, g_wkq1, g_wkq2, g_s_wk,
                     nullptr, g_kr_hi, g_kr_lo, cosb, sinb, 1, KVDIM,
                     bm, (y - 32) * 128, smem);
    } else {
        gemm_i8_body(g_hq1, g_hq2, g_s_hid, g_wvq1, g_wvq2, g_s_wv,
                     g_v, nullptr, nullptr, nullptr, nullptr, 0, KVDIM,
                     bm, (y - 40) * 128, smem);
    }
}

__global__ __launch_bounds__(256, 1) void gemm_o_i8(float* __restrict__ out) {
    extern __shared__ char smem[];
    gemm_i8_body(g_atq1, g_atq2, g_s_at, g_woq1, g_woq2, g_s_wo,
                 out, nullptr, nullptr, nullptr, nullptr, 0, HID,
                 blockIdx.x * 128, blockIdx.y * 128, smem);
}

// ---------------------------------------------------------------------------
// transpose + split: v[S,1024] fp32 -> vT hi/lo [1024, S]
// ---------------------------------------------------------------------------
__global__ void transpose_split(const float* __restrict__ v,
                                __nv_bfloat16* __restrict__ th,
                                __nv_bfloat16* __restrict__ tl) {
    __shared__ float tile[32][33];
    const int bs = blockIdx.x * 32;
    const int bd = blockIdx.y * 32;
    const int tx = threadIdx.x;
    const int ty = threadIdx.y;
#pragma unroll
    for (int i = 0; i < 4; i++) {
        int sy = ty * 4 + i;
        tile[sy][tx] = v[(size_t)(bs + sy) * KVDIM + bd + tx];
    }
    __syncthreads();
#pragma unroll
    for (int i = 0; i < 4; i++) {
        int dy = ty * 4 + i;
        float val = tile[tx][dy];
        __nv_bfloat16 h = __float2bfloat16(val);
        __nv_bfloat16 l = __float2bfloat16(val - __bfloat162float(h));
        th[(size_t)(bd + dy) * S_LEN + bs + tx] = h;
        tl[(size_t)(bd + dy) * S_LEN + bs + tx] = l;
    }
}

// ---------------------------------------------------------------------------
// Flash attention (bf16x3, warp MMA). BQ=64, 128 threads, Q in registers.
// K double-buffered / V pipelined. 106.5KB SMEM -> 2 CTAs/SM. exp2 softmax.
// Writes fp32 attn. Grid (32 qb reversed, 32 h).
// ---------------------------------------------------------------------------
#define QLDT 272
#define VLDT 144
#define FK0  0
#define FK1  34816
#define FV   69632
#define FLASH_SMEM (FV + 36864)   // 106496

__global__ __launch_bounds__(128, 2) void flash_tc(
    const __nv_bfloat16* __restrict__ qh, const __nv_bfloat16* __restrict__ ql,
    const __nv_bfloat16* __restrict__ kh, const __nv_bfloat16* __restrict__ kl,
    const __nv_bfloat16* __restrict__ vth, const __nv_bfloat16* __restrict__ vtl,
    float* __restrict__ o) {
    extern __shared__ char sm[];
    const int qb = (int)gridDim.x - 1 - (int)blockIdx.x;
    const int h  = blockIdx.y;
    const int kvh = h >> 2;
    const int tid = threadIdx.x;
    const int lane = tid & 31;
    const int w = tid >> 5;
    const int q0 = qb * 64;
    const float scale2 = 0.12751744685137577f;   // scale * log2(e)
    uint32_t sb = (uint32_t)__cvta_generic_to_shared(sm);

    const int brow = (lane & 7) + ((lane >> 4) << 3);
    const int bch = (lane >> 3) & 1;

    for (int i = tid; i < 2048; i += 128) {
        int mat = i >> 10;
        int idx = i & 1023;
        int r = idx >> 4;
        int c = idx & 15;
        const __nv_bfloat16* src = (mat ? ql : qh) + (size_t)(q0 + r) * HID + h * HD + c * 8;
        *(uint4*)(sm + FK1 + mat * 17408 + r * QLDT + c * 16) = *(const uint4*)src;
    }
    __syncthreads();
    uint32_t qfh[8][4], qfl[8][4];
#pragma unroll
    for (int kf = 0; kf < 8; kf++) {
        uint32_t aoff = (uint32_t)((w * 16 + (lane & 15)) * QLDT + kf * 32 + (lane >> 4) * 16);
        ldsm_x4(sb + FK1 + aoff, qfh[kf][0], qfh[kf][1], qfh[kf][2], qfh[kf][3]);
        ldsm_x4(sb + FK1 + 17408 + aoff, qfl[kf][0], qfl[kf][1], qfl[kf][2], qfl[kf][3]);
    }
    __syncthreads();

    auto loadK = [&](int kb) {
        const int k0 = kb * 64;
        uint32_t kdst = sb + ((kb & 1) ? FK1 : FK0);
#pragma unroll
        for (int i0 = 0; i0 < 16; i0++) {
            int i = tid + i0 * 128;
            int mat = i >> 10;
            int idx = i & 1023;
            int r = idx >> 4;
            int c = idx & 15;
            const void* src = (mat ? kl : kh) + (size_t)(k0 + r) * KVDIM + kvh * HD + c * 8;
            asm volatile("cp.async.cg.shared.global [%0], [%1], 16;"
                         :: "r"(kdst + mat * 17408 + r * QLDT + c * 16), "l"(src));
        }
        asm volatile("cp.async.commit_group;");
    };
    auto loadV = [&](int kb) {
        const int k0 = kb * 64;
        uint32_t vdst = sb + FV;
#pragma unroll
        for (int i0 = 0; i0 < 16; i0++) {
            int i = tid + i0 * 128;
            int mat = i >> 10;
            int idx = i & 1023;
            int r = idx >> 3;
            int c = idx & 7;
            const void* src = (mat ? vtl : vth) + (size_t)(kvh * HD + r) * S_LEN + k0 + c * 8;
            asm volatile("cp.async.cg.shared.global [%0], [%1], 16;"
                         :: "r"(vdst + mat * 18432 + r * VLDT + c * 16), "l"(src));
        }
        asm volatile("cp.async.commit_group;");
    };

    float m0 = -1e30f, m1 = -1e30f, l0 = 0.f, l1 = 0.f;
    float oa[16][4];
#pragma unroll
    for (int i = 0; i < 16; i++)
#pragma unroll
        for (int t = 0; t < 4; t++) oa[i][t] = 0.f;

    const int r0g = q0 + w * 16 + (lane >> 2);
    const int r1g = r0g + 8;

    loadK(0);

    for (int kb = 0; kb <= qb; kb++) {
        const int k0 = kb * 64;
        loadV(kb);
        if (kb < qb) loadK(kb + 1);
        else         asm volatile("cp.async.commit_group;");
        asm volatile("cp.async.wait_group 2;");
        __syncthreads();

        const uint32_t kbase = sb + ((kb & 1) ? FK1 : FK0);

        float s[8][4];
#pragma unroll
        for (int nf = 0; nf < 8; nf++)
#pragma unroll
            for (int t = 0; t < 4; t++) s[nf][t] = 0.f;

#pragma unroll
        for (int kf = 0; kf < 8; kf++) {
#pragma unroll
            for (int np = 0; np < 4; np++) {
                uint32_t boff = (uint32_t)((np * 16 + brow) * QLDT + kf * 32 + bch * 16);
                uint32_t bh[4], bl[4];
                ldsm_x4(kbase + boff, bh[0], bh[1], bh[2], bh[3]);
                ldsm_x4(kbase + 17408 + boff, bl[0], bl[1], bl[2], bl[3]);
                mma_bf16(s[np * 2], qfh[kf], bh);
                mma_bf16(s[np * 2], qfh[kf], bl);
                mma_bf16(s[np * 2], qfl[kf], bh);
                mma_bf16(s[np * 2 + 1], qfh[kf], bh + 2);
                mma_bf16(s[np * 2 + 1], qfh[kf], bl + 2);
                mma_bf16(s[np * 2 + 1], qfl[kf], bh + 2);
            }
        }

#pragma unroll
        for (int nf = 0; nf < 8; nf++)
#pragma unroll
            for (int t = 0; t < 4; t++) s[nf][t] *= scale2;
        if (kb == qb) {
#pragma unroll
            for (int nf = 0; nf < 8; nf++) {
                int cg = k0 + nf * 8 + (lane & 3) * 2;
                if (cg > r0g)     s[nf][0] = -1e30f;
                if (cg + 1 > r0g) s[nf][1] = -1e30f;
                if (cg > r1g)     s[nf][2] = -1e30f;
                if (cg + 1 > r1g) s[nf][3] = -1e30f;
            }
        }

        float mx0 = -1e30f, mx1 = -1e30f;
#pragma unroll
        for (int nf = 0; nf < 8; nf++) {
            mx0 = fmaxf(mx0, fmaxf(s[nf][0], s[nf][1]));
            mx1 = fmaxf(mx1, fmaxf(s[nf][2], s[nf][3]));
        }
        mx0 = fmaxf(mx0, __shfl_xor_sync(0xffffffffu, mx0, 1));
        mx0 = fmaxf(mx0, __shfl_xor_sync(0xffffffffu, mx0, 2));
        mx1 = fmaxf(mx1, __shfl_xor_sync(0xffffffffu, mx1, 1));
        mx1 = fmaxf(mx1, __shfl_xor_sync(0xffffffffu, mx1, 2));
        float mn0 = fmaxf(m0, mx0);
        float mn1 = fmaxf(m1, mx1);
        float c0 = exp2f(m0 - mn0);
        float c1 = exp2f(m1 - mn1);
        m0 = mn0; m1 = mn1;
        float rs0 = 0.f, rs1 = 0.f;
#pragma unroll
        for (int nf = 0; nf < 8; nf++) {
            s[nf][0] = exp2f(s[nf][0] - m0); rs0 += s[nf][0];
            s[nf][1] = exp2f(s[nf][1] - m0); rs0 += s[nf][1];
            s[nf][2] = exp2f(s[nf][2] - m1); rs1 += s[nf][2];
            s[nf][3] = exp2f(s[nf][3] - m1); rs1 += s[nf][3];
        }
        rs0 += __shfl_xor_sync(0xffffffffu, rs0, 1);
        rs0 += __shfl_xor_sync(0xffffffffu, rs0, 2);
        rs1 += __shfl_xor_sync(0xffffffffu, rs1, 1);
        rs1 += __shfl_xor_sync(0xffffffffu, rs1, 2);
        l0 = l0 * c0 + rs0;
        l1 = l1 * c1 + rs1;
#pragma unroll
        for (int i = 0; i < 16; i++) {
            oa[i][0] *= c0; oa[i][1] *= c0;
            oa[i][2] *= c1; oa[i][3] *= c1;
        }

        asm volatile("cp.async.wait_group 1;");
        __syncthreads();

#pragma unroll
        for (int kf2 = 0; kf2 < 4; kf2++) {
            uint32_t pah[4], pal[4];
            pah[0] = pack_hl(s[2 * kf2][0], s[2 * kf2][1], pal[0]);
            pah[1] = pack_hl(s[2 * kf2][2], s[2 * kf2][3], pal[1]);
            pah[2] = pack_hl(s[2 * kf2 + 1][0], s[2 * kf2 + 1][1], pal[2]);
            pah[3] = pack_hl(s[2 * kf2 + 1][2], s[2 * kf2 + 1][3], pal[3]);
#pragma unroll
            for (int np = 0; np < 8; np++) {
                uint32_t voff = (uint32_t)((np * 16 + brow) * VLDT + kf2 * 32 + bch * 16);
                uint32_t vh[4], vl[4];
                ldsm_x4(sb + FV + voff, vh[0], vh[1], vh[2], vh[3]);
                ldsm_x4(sb + FV + 18432 + voff, vl[0], vl[1], vl[2], vl[3]);
                mma_bf16(oa[np * 2], pah, vh);
                mma_bf16(oa[np * 2], pah, vl);
                mma_bf16(oa[np * 2], pal, vh);
                mma_bf16(oa[np * 2 + 1], pah, vh + 2);
                mma_bf16(oa[np * 2 + 1], pah, vl + 2);
                mma_bf16(oa[np * 2 + 1], pal, vh + 2);
            }
        }
        __syncthreads();
    }

    const float inv0 = 1.0f / l0;
    const float inv1 = 1.0f / l1;
#pragma unroll
    for (int nf2 = 0; nf2 < 16; nf2++) {
        int col = h * HD + nf2 * 8 + (lane & 3) * 2;
        *(float2*)&o[(size_t)r0g * HID + col] = make_float2(oa[nf2][0] * inv0, oa[nf2][1] * inv0);
        *(float2*)&o[(size_t)r1g * HID + col] = make_float2(oa[nf2][2] * inv1, oa[nf2][3] * inv1);
    }
}

// ---------------------------------------------------------------------------
// launcher
// ---------------------------------------------------------------------------
extern "C" void kernel_launch(void* const* d_in, const int* in_sizes, int n_in,
                              void* d_out, int out_size) {
    const float* hidden = (const float*)d_in[0];
    const float* cosb = (const float*)d_in[2];
    const float* sinb = (const float*)d_in[3];
    const float* wq = (const float*)d_in[4];
    const float* wk = (const float*)d_in[5];
    const float* wv = (const float*)d_in[6];
    const float* wo = (const float*)d_in[7];
    float* out = (float*)d_out;

    float* v;
    cudaGetSymbolAddress((void**)&v, g_v);
    __nv_bfloat16 *qr_hi, *qr_lo, *kr_hi, *kr_lo, *vt_hi, *vt_lo;
    float* attn;
    cudaGetSymbolAddress((void**)&attn, g_attn);
    cudaGetSymbolAddress((void**)&qr_hi, g_qr_hi);
    cudaGetSymbolAddress((void**)&qr_lo, g_qr_lo);
    cudaGetSymbolAddress((void**)&kr_hi, g_kr_hi);
    cudaGetSymbolAddress((void**)&kr_lo, g_kr_lo);
    cudaGetSymbolAddress((void**)&vt_hi, g_vt_hi);
    cudaGetSymbolAddress((void**)&vt_lo, g_vt_lo);

    // quantize hidden + all weights (12288 rows)
    quant_all<<<12288, 256>>>(hidden, wq, wk, wv, wo);

    cudaFuncSetAttribute(gemm_qkv_i8, cudaFuncAttributeMaxDynamicSharedMemorySize,
                         ISMEM);
    cudaFuncSetAttribute(gemm_o_i8, cudaFuncAttributeMaxDynamicSharedMemorySize,
                         ISMEM);

    // fused QKV projection (int8): 48 N-tiles = 32 Q + 8 K + 8 V
    gemm_qkv_i8<<<dim3(S_LEN / 128, 48), 256, ISMEM>>>(cosb, sinb);

    // V transpose + split
    transpose_split<<<dim3(S_LEN / 32, KVDIM / 32), dim3(32, 8)>>>(v, vt_hi, vt_lo);

    // flash attention (bf16x3), writes fp32 attn
    cudaFuncSetAttribute(flash_tc, cudaFuncAttributeMaxDynamicSharedMemorySize,
                         FLASH_SMEM);
    flash_tc<<<dim3(32, 32), 128, FLASH_SMEM>>>(qr_hi, qr_lo, kr_hi, kr_lo,
                                                vt_hi, vt_lo, attn);

    // quantize attn rows, then int8 output projection
    quant_attn<<<2048, 256>>>();
    gemm_o_i8<<<dim3(S_LEN / 128, HID / 128), 256, ISMEM>>>(out);
}

// round 12
// speedup vs baseline: 3.3524x; 3.3524x over previous
#include <cuda_runtime.h>
#include <cuda_bf16.h>
#include <cuda_fp16.h>
#include <stdint.h>

// ---------------------------------------------------------------------------
// LlamaAttention: S=2048, HID=4096, NH=32, NKV=8, D=128
// Projections: fp16x2 warp-MMA GEMM (A fp16 single, B fp16 hi+lo; 2 MMAs).
// Attention: bf16x3 warp-MMA flash (R10 config: 2 CTA/SM, pipelined, exp2).
// RoPE fused in QKV epilogue. tcgen05/IMMA unavailable or slow; HMMA only.
// ---------------------------------------------------------------------------

#define S_LEN 2048
#define HID   4096
#define NH    32
#define NKV   8
#define HD    128
#define KVDIM (NKV * HD)   // 1024
#define KDIM  4096

// fp32 scratch (V only)
__device__ float g_v[S_LEN * KVDIM];

// fp16 GEMM operands
__device__ __half g_h1[S_LEN * KDIM];                      // hidden (single)
__device__ __half g_wq1[HID * KDIM],   g_wq2[HID * KDIM];
__device__ __half g_wk1[KVDIM * KDIM], g_wk2[KVDIM * KDIM];
__device__ __half g_wv1[KVDIM * KDIM], g_wv2[KVDIM * KDIM];
__device__ __half g_wo1[HID * KDIM],   g_wo2[HID * KDIM];
__device__ __half g_at1[S_LEN * KDIM];                     // attn (single)

// bf16 attention operands
__device__ __nv_bfloat16 g_qr_hi[S_LEN * HID];
__device__ __nv_bfloat16 g_qr_lo[S_LEN * HID];
__device__ __nv_bfloat16 g_kr_hi[S_LEN * KVDIM];
__device__ __nv_bfloat16 g_kr_lo[S_LEN * KVDIM];
__device__ __nv_bfloat16 g_vt_hi[KVDIM * S_LEN];
__device__ __nv_bfloat16 g_vt_lo[KVDIM * S_LEN];

__device__ __forceinline__ uint32_t pack_hl(float f0, float f1, uint32_t& lo) {
    __nv_bfloat162 h = __floats2bfloat162_rn(f0, f1);
    float r0 = f0 - __bfloat162float(h.x);
    float r1 = f1 - __bfloat162float(h.y);
    __nv_bfloat162 l = __floats2bfloat162_rn(r0, r1);
    lo = *(uint32_t*)&l;
    return *(uint32_t*)&h;
}

// ---------------------------------------------------------------------------
// fused split: hidden (fp16 single) + 4 weights (fp16 pair). 8 elems/thread.
// ---------------------------------------------------------------------------
#define N_HID (S_LEN * KDIM)
#define N_WQ  (HID * KDIM)
#define N_WKV (KVDIM * KDIM)
#define SEG0  N_HID
#define SEG1  (SEG0 + N_WQ)
#define SEG2  (SEG1 + N_WKV)
#define SEG3  (SEG2 + N_WKV)
#define SEG4  (SEG3 + N_WQ)
#define SPLIT_GRID (SEG4 / (8 * 256))

__device__ __forceinline__ void split8_pair(const float* src, __half* h1,
                                            __half* h2, int off) {
    float4 f[2];
    f[0] = *(const float4*)(src + off);
    f[1] = *(const float4*)(src + off + 4);
    __half2 o1[4], o2[4];
#pragma unroll
    for (int j = 0; j < 2; j++) {
        const float v[4] = {f[j].x, f[j].y, f[j].z, f[j].w};
#pragma unroll
        for (int p = 0; p < 2; p++) {
            __half a = __float2half_rn(v[p * 2]);
            __half b = __float2half_rn(v[p * 2 + 1]);
            __half ra = __float2half_rn(v[p * 2] - __half2float(a));
            __half rb = __float2half_rn(v[p * 2 + 1] - __half2float(b));
            o1[j * 2 + p] = __halves2half2(a, b);
            o2[j * 2 + p] = __halves2half2(ra, rb);
        }
    }
    *(uint4*)(h1 + off) = *(uint4*)o1;
    *(uint4*)(h2 + off) = *(uint4*)o2;
}

__device__ __forceinline__ void split8_single(const float* src, __half* h1, int off) {
    float4 f[2];
    f[0] = *(const float4*)(src + off);
    f[1] = *(const float4*)(src + off + 4);
    __half2 o1[4];
    o1[0] = __floats2half2_rn(f[0].x, f[0].y);
    o1[1] = __floats2half2_rn(f[0].z, f[0].w);
    o1[2] = __floats2half2_rn(f[1].x, f[1].y);
    o1[3] = __floats2half2_rn(f[1].z, f[1].w);
    *(uint4*)(h1 + off) = *(uint4*)o1;
}

__global__ void split_all(const float* __restrict__ hidden,
                          const float* __restrict__ wq,
                          const float* __restrict__ wk,
                          const float* __restrict__ wv,
                          const float* __restrict__ wo) {
    int g = (blockIdx.x * blockDim.x + threadIdx.x) * 8;
    if (g < SEG0)      split8_single(hidden, g_h1, g);
    else if (g < SEG1) split8_pair(wq, g_wq1, g_wq2, g - SEG0);
    else if (g < SEG2) split8_pair(wk, g_wk1, g_wk2, g - SEG1);
    else if (g < SEG3) split8_pair(wv, g_wv1, g_wv2, g - SEG2);
    else               split8_pair(wo, g_wo1, g_wo2, g - SEG3);
}

// ---------------------------------------------------------------------------
// warp-MMA primitives
// ---------------------------------------------------------------------------
__device__ __forceinline__ void ldsm_x4(uint32_t addr, uint32_t& r0, uint32_t& r1,
                                        uint32_t& r2, uint32_t& r3) {
    asm volatile("ldmatrix.sync.aligned.m8n8.x4.shared.b16 {%0,%1,%2,%3}, [%4];"
                 : "=r"(r0), "=r"(r1), "=r"(r2), "=r"(r3) : "r"(addr));
}

__device__ __forceinline__ void mma_bf16(float* c, const uint32_t* a, const uint32_t* b) {
    asm volatile(
        "mma.sync.aligned.m16n8k16.row.col.f32.bf16.bf16.f32 "
        "{%0,%1,%2,%3},{%4,%5,%6,%7},{%8,%9},{%0,%1,%2,%3};"
        : "+f"(c[0]), "+f"(c[1]), "+f"(c[2]), "+f"(c[3])
        : "r"(a[0]), "r"(a[1]), "r"(a[2]), "r"(a[3]), "r"(b[0]), "r"(b[1]));
}

__device__ __forceinline__ void mma_f16(float* c, const uint32_t* a, const uint32_t* b) {
    asm volatile(
        "mma.sync.aligned.m16n8k16.row.col.f32.f16.f16.f32 "
        "{%0,%1,%2,%3},{%4,%5,%6,%7},{%8,%9},{%0,%1,%2,%3};"
        : "+f"(c[0]), "+f"(c[1]), "+f"(c[2]), "+f"(c[3])
        : "r"(a[0]), "r"(a[1]), "r"(a[2]), "r"(a[3]), "r"(b[0]), "r"(b[1]));
}

// ---------------------------------------------------------------------------
// fp16x2 GEMM body: C = A1·B1 + A1·B2. Block 256x128, warp 64x64, BK=64,
// 256 threads, 2-stage cp.async, 144B-padded rows.
// Epilogue: 0 = fp32 store, 1 = RoPE + bf16 hi/lo split store.
// ---------------------------------------------------------------------------
#define GBK  64
#define LDT  144
#define A_T  (256 * LDT)                 // 36864
#define B_T  (128 * LDT)                 // 18432
#define STG  (A_T + 2 * B_T)             // 73728
#define GEMM_SMEM (2 * STG)              // 147456

__device__ __forceinline__ void gemm_body_f16(
    const __half* __restrict__ A1,
    const __half* __restrict__ B1, const __half* __restrict__ B2,
    float* __restrict__ Cf, __nv_bfloat16* __restrict__ Chi,
    __nv_bfloat16* __restrict__ Clo,
    const float* __restrict__ cosb, const float* __restrict__ sinb,
    int mode, int N, int bm, int bn, char* smem) {
    const int tid = threadIdx.x;
    const int lane = tid & 31;
    const int warp = tid >> 5;
    const int wr = warp >> 1;     // 0..3 (64-row slices)
    const int wc = warp & 1;      // 0..1 (64-col slices)
    uint32_t sbase = (uint32_t)__cvta_generic_to_shared(smem);

    float acc[4][8][4];
#pragma unroll
    for (int mi = 0; mi < 4; mi++)
#pragma unroll
        for (int ni = 0; ni < 8; ni++)
#pragma unroll
            for (int t = 0; t < 4; t++) acc[mi][ni][t] = 0.f;

    auto load_stage = [&](int s, int it) {
        const int kbase = it * GBK;
        uint32_t dst0 = sbase + s * STG;
#pragma unroll
        for (int i = 0; i < 16; i++) {
            int c = tid + i * 256;     // 0..4095 16B chunks
            const __half* gsrc;
            uint32_t daddr;
            if (c < 2048) {            // A1: 256 rows x 8 chunks
                int row = c >> 3;
                int ch = c & 7;
                gsrc = A1 + (size_t)(bm + row) * KDIM + kbase + ch * 8;
                daddr = dst0 + row * LDT + ch * 16;
            } else {                   // B1 then B2: 128 rows x 8 chunks each
                int cb = c - 2048;
                int mat = cb >> 10;
                int idx = cb & 1023;
                int row = idx >> 3;
                int ch = idx & 7;
                gsrc = (mat ? B2 : B1) + (size_t)(bn + row) * KDIM + kbase + ch * 8;
                daddr = dst0 + A_T + mat * B_T + row * LDT + ch * 16;
            }
            asm volatile("cp.async.cg.shared.global [%0], [%1], 16;"
                         :: "r"(daddr), "l"(gsrc));
        }
        asm volatile("cp.async.commit_group;");
    };

    const int NIT = KDIM / GBK;   // 64
    load_stage(0, 0);
    load_stage(1, 1);

    const int brow = (lane & 7) + ((lane >> 4) << 3);
    const int bch = (lane >> 3) & 1;

    for (int it = 0; it < NIT; it++) {
        asm volatile("cp.async.wait_group 1;");
        __syncthreads();

        uint32_t sa = sbase + (it & 1) * STG;
#pragma unroll
        for (int ks = 0; ks < 4; ks++) {
            uint32_t af[4][4];
#pragma unroll
            for (int mi = 0; mi < 4; mi++) {
                uint32_t off = (uint32_t)((wr * 64 + mi * 16 + (lane & 15)) * LDT +
                                          ks * 32 + ((lane >> 4) & 1) * 16);
                ldsm_x4(sa + off, af[mi][0], af[mi][1], af[mi][2], af[mi][3]);
            }
#pragma unroll
            for (int half = 0; half < 2; half++) {
                uint32_t b1[4][2], b2[4][2];
#pragma unroll
                for (int np = 0; np < 2; np++) {
                    uint32_t off = (uint32_t)((wc * 64 + half * 32 + np * 16 + brow) * LDT +
                                              ks * 32 + bch * 16);
                    uint32_t r0, r1, r2, r3;
                    ldsm_x4(sa + A_T + off, r0, r1, r2, r3);
                    b1[np * 2][0] = r0; b1[np * 2][1] = r1;
                    b1[np * 2 + 1][0] = r2; b1[np * 2 + 1][1] = r3;
                    ldsm_x4(sa + A_T + B_T + off, r0, r1, r2, r3);
                    b2[np * 2][0] = r0; b2[np * 2][1] = r1;
                    b2[np * 2 + 1][0] = r2; b2[np * 2 + 1][1] = r3;
                }
#pragma unroll
                for (int mi = 0; mi < 4; mi++)
#pragma unroll
                    for (int nf = 0; nf < 4; nf++) {
                        float* a = acc[mi][half * 4 + nf];
                        mma_f16(a, af[mi], b1[nf]);
                        mma_f16(a, af[mi], b2[nf]);
                    }
            }
        }
        __syncthreads();
        if (it + 2 < NIT) load_stage(it & 1, it + 2);
        else              asm volatile("cp.async.commit_group;");
    }

    if (mode == 0) {
#pragma unroll
        for (int mi = 0; mi < 4; mi++) {
            const int r0 = bm + wr * 64 + mi * 16 + (lane >> 2);
#pragma unroll
            for (int ni = 0; ni < 8; ni++) {
                const int col = bn + wc * 64 + ni * 8 + (lane & 3) * 2;
                *(float2*)&Cf[(size_t)r0 * N + col] = make_float2(acc[mi][ni][0], acc[mi][ni][1]);
                *(float2*)&Cf[(size_t)(r0 + 8) * N + col] = make_float2(acc[mi][ni][2], acc[mi][ni][3]);
            }
        }
    } else {
        // RoPE + bf16 hi/lo split epilogue (Q/K)
#pragma unroll
        for (int mi = 0; mi < 4; mi++) {
            const int r0 = bm + wr * 64 + mi * 16 + (lane >> 2);
            const int r1 = r0 + 8;
#pragma unroll
            for (int ni = 0; ni < 8; ni++) {
                const int col = bn + wc * 64 + ni * 8 + (lane & 3) * 2;
                const int i = (col & 127) >> 1;
                float c0 = cosb[r0 * 64 + i], s0 = sinb[r0 * 64 + i];
                float c1 = cosb[r1 * 64 + i], s1 = sinb[r1 * 64 + i];
                float a0 = acc[mi][ni][0], b0 = acc[mi][ni][1];
                float a1 = acc[mi][ni][2], b1 = acc[mi][ni][3];
                float x0 = a0 * c0 - b0 * s0, y0 = a0 * s0 + b0 * c0;
                float x1 = a1 * c1 - b1 * s1, y1 = a1 * s1 + b1 * c1;
                uint32_t lo32, hi32;
                hi32 = pack_hl(x0, y0, lo32);
                *(uint32_t*)&Chi[(size_t)r0 * N + col] = hi32;
                *(uint32_t*)&Clo[(size_t)r0 * N + col] = lo32;
                hi32 = pack_hl(x1, y1, lo32);
                *(uint32_t*)&Chi[(size_t)r1 * N + col] = hi32;
                *(uint32_t*)&Clo[(size_t)r1 * N + col] = lo32;
            }
        }
    }
}

// fused QKV: grid (8, 48). y<32: Q (RoPE); y<40: K (RoPE); else V (fp32).
__global__ __launch_bounds__(256, 1) void gemm_qkv(const float* __restrict__ cosb,
                                                   const float* __restrict__ sinb) {
    extern __shared__ char smem[];
    const int y = blockIdx.y;
    const int bm = blockIdx.x * 256;
    if (y < 32) {
        gemm_body_f16(g_h1, g_wq1, g_wq2, nullptr, g_qr_hi, g_qr_lo,
                      cosb, sinb, 1, HID, bm, y * 128, smem);
    } else if (y < 40) {
        gemm_body_f16(g_h1, g_wk1, g_wk2, nullptr, g_kr_hi, g_kr_lo,
                      cosb, sinb, 1, KVDIM, bm, (y - 32) * 128, smem);
    } else {
        gemm_body_f16(g_h1, g_wv1, g_wv2, g_v, nullptr, nullptr,
                      nullptr, nullptr, 0, KVDIM, bm, (y - 40) * 128, smem);
    }
}

__global__ __launch_bounds__(256, 1) void gemm_o(float* __restrict__ out) {
    extern __shared__ char smem[];
    gemm_body_f16(g_at1, g_wo1, g_wo2, out, nullptr, nullptr,
                  nullptr, nullptr, 0, HID, blockIdx.x * 256, blockIdx.y * 128, smem);
}

// ---------------------------------------------------------------------------
// transpose + split: v[S,1024] fp32 -> vT hi/lo [1024, S] bf16
// ---------------------------------------------------------------------------
__global__ void transpose_split(const float* __restrict__ v,
                                __nv_bfloat16* __restrict__ th,
                                __nv_bfloat16* __restrict__ tl) {
    __shared__ float tile[32][33];
    const int bs = blockIdx.x * 32;
    const int bd = blockIdx.y * 32;
    const int tx = threadIdx.x;
    const int ty = threadIdx.y;
#pragma unroll
    for (int i = 0; i < 4; i++) {
        int sy = ty * 4 + i;
        tile[sy][tx] = v[(size_t)(bs + sy) * KVDIM + bd + tx];
    }
    __syncthreads();
#pragma unroll
    for (int i = 0; i < 4; i++) {
        int dy = ty * 4 + i;
        float val = tile[tx][dy];
        __nv_bfloat16 h = __float2bfloat16(val);
        __nv_bfloat16 l = __float2bfloat16(val - __bfloat162float(h));
        th[(size_t)(bd + dy) * S_LEN + bs + tx] = h;
        tl[(size_t)(bd + dy) * S_LEN + bs + tx] = l;
    }
}

// ---------------------------------------------------------------------------
// Flash attention (bf16x3, warp MMA). BQ=64, 128 threads, Q in registers.
// K double-buffered / V pipelined. 106.5KB SMEM -> 2 CTAs/SM. exp2 softmax.
// Chunk-interleaved pack+PV. Writes fp16 attn. Grid (32 qb reversed, 32 h).
// ---------------------------------------------------------------------------
#define QLDT 272
#define VLDT 144
#define FK0  0
#define FK1  34816
#define FV   69632
#define FLASH_SMEM (FV + 36864)   // 106496

__global__ __launch_bounds__(128, 2) void flash_tc(
    const __nv_bfloat16* __restrict__ qh, const __nv_bfloat16* __restrict__ ql,
    const __nv_bfloat16* __restrict__ kh, const __nv_bfloat16* __restrict__ kl,
    const __nv_bfloat16* __restrict__ vth, const __nv_bfloat16* __restrict__ vtl,
    __half* __restrict__ o1) {
    extern __shared__ char sm[];
    const int qb = (int)gridDim.x - 1 - (int)blockIdx.x;
    const int h  = blockIdx.y;
    const int kvh = h >> 2;
    const int tid = threadIdx.x;
    const int lane = tid & 31;
    const int w = tid >> 5;
    const int q0 = qb * 64;
    const float scale2 = 0.12751744685137577f;   // (1/sqrt(128)) * log2(e)
    uint32_t sb = (uint32_t)__cvta_generic_to_shared(sm);

    const int brow = (lane & 7) + ((lane >> 4) << 3);
    const int bch = (lane >> 3) & 1;

    for (int i = tid; i < 2048; i += 128) {
        int mat = i >> 10;
        int idx = i & 1023;
        int r = idx >> 4;
        int c = idx & 15;
        const __nv_bfloat16* src = (mat ? ql : qh) + (size_t)(q0 + r) * HID + h * HD + c * 8;
        *(uint4*)(sm + FK1 + mat * 17408 + r * QLDT + c * 16) = *(const uint4*)src;
    }
    __syncthreads();
    uint32_t qfh[8][4], qfl[8][4];
#pragma unroll
    for (int kf = 0; kf < 8; kf++) {
        uint32_t aoff = (uint32_t)((w * 16 + (lane & 15)) * QLDT + kf * 32 + (lane >> 4) * 16);
        ldsm_x4(sb + FK1 + aoff, qfh[kf][0], qfh[kf][1], qfh[kf][2], qfh[kf][3]);
        ldsm_x4(sb + FK1 + 17408 + aoff, qfl[kf][0], qfl[kf][1], qfl[kf][2], qfl[kf][3]);
    }
    __syncthreads();

    auto loadK = [&](int kb) {
        const int k0 = kb * 64;
        uint32_t kdst = sb + ((kb & 1) ? FK1 : FK0);
#pragma unroll
        for (int i0 = 0; i0 < 16; i0++) {
            int i = tid + i0 * 128;
            int mat = i >> 10;
            int idx = i & 1023;
            int r = idx >> 4;
            int c = idx & 15;
            const void* src = (mat ? kl : kh) + (size_t)(k0 + r) * KVDIM + kvh * HD + c * 8;
            asm volatile("cp.async.cg.shared.global [%0], [%1], 16;"
                         :: "r"(kdst + mat * 17408 + r * QLDT + c * 16), "l"(src));
        }
        asm volatile("cp.async.commit_group;");
    };
    auto loadV = [&](int kb) {
        const int k0 = kb * 64;
        uint32_t vdst = sb + FV;
#pragma unroll
        for (int i0 = 0; i0 < 16; i0++) {
            int i = tid + i0 * 128;
            int mat = i >> 10;
            int idx = i & 1023;
            int r = idx >> 3;
            int c = idx & 7;
            const void* src = (mat ? vtl : vth) + (size_t)(kvh * HD + r) * S_LEN + k0 + c * 8;
            asm volatile("cp.async.cg.shared.global [%0], [%1], 16;"
                         :: "r"(vdst + mat * 18432 + r * VLDT + c * 16), "l"(src));
        }
        asm volatile("cp.async.commit_group;");
    };

    float m0 = -1e30f, m1 = -1e30f, l0 = 0.f, l1 = 0.f;
    float oa[16][4];
#pragma unroll
    for (int i = 0; i < 16; i++)
#pragma unroll
        for (int t = 0; t < 4; t++) oa[i][t] = 0.f;

    const int r0g = q0 + w * 16 + (lane >> 2);
    const int r1g = r0g + 8;

    loadK(0);

    for (int kb = 0; kb <= qb; kb++) {
        const int k0 = kb * 64;
        loadV(kb);
        if (kb < qb) loadK(kb + 1);
        else         asm volatile("cp.async.commit_group;");
        asm volatile("cp.async.wait_group 2;");
        __syncthreads();

        const uint32_t kbase = sb + ((kb & 1) ? FK1 : FK0);

        float s[8][4];
#pragma unroll
        for (int nf = 0; nf < 8; nf++)
#pragma unroll
            for (int t = 0; t < 4; t++) s[nf][t] = 0.f;

#pragma unroll
        for (int kf = 0; kf < 8; kf++) {
#pragma unroll
            for (int np = 0; np < 4; np++) {
                uint32_t boff = (uint32_t)((np * 16 + brow) * QLDT + kf * 32 + bch * 16);
                uint32_t bh[4], bl[4];
                ldsm_x4(kbase + boff, bh[0], bh[1], bh[2], bh[3]);
                ldsm_x4(kbase + 17408 + boff, bl[0], bl[1], bl[2], bl[3]);
                mma_bf16(s[np * 2], qfh[kf], bh);
                mma_bf16(s[np * 2], qfh[kf], bl);
                mma_bf16(s[np * 2], qfl[kf], bh);
                mma_bf16(s[np * 2 + 1], qfh[kf], bh + 2);
                mma_bf16(s[np * 2 + 1], qfh[kf], bl + 2);
                mma_bf16(s[np * 2 + 1], qfl[kf], bh + 2);
            }
        }

#pragma unroll
        for (int nf = 0; nf < 8; nf++)
#pragma unroll
            for (int t = 0; t < 4; t++) s[nf][t] *= scale2;
        if (kb == qb) {
#pragma unroll
            for (int nf = 0; nf < 8; nf++) {
                int cg = k0 + nf * 8 + (lane & 3) * 2;
                if (cg > r0g)     s[nf][0] = -1e30f;
                if (cg + 1 > r0g) s[nf][1] = -1e30f;
                if (cg > r1g)     s[nf][2] = -1e30f;
                if (cg + 1 > r1g) s[nf][3] = -1e30f;
            }
        }

        float mx0 = -1e30f, mx1 = -1e30f;
#pragma unroll
        for (int nf = 0; nf < 8; nf++) {
            mx0 = fmaxf(mx0, fmaxf(s[nf][0], s[nf][1]));
            mx1 = fmaxf(mx1, fmaxf(s[nf][2], s[nf][3]));
        }
        mx0 = fmaxf(mx0, __shfl_xor_sync(0xffffffffu, mx0, 1));
        mx0 = fmaxf(mx0, __shfl_xor_sync(0xffffffffu, mx0, 2));
        mx1 = fmaxf(mx1, __shfl_xor_sync(0xffffffffu, mx1, 1));
        mx1 = fmaxf(mx1, __shfl_xor_sync(0xffffffffu, mx1, 2));
        float mn0 = fmaxf(m0, mx0);
        float mn1 = fmaxf(m1, mx1);
        float c0 = exp2f(m0 - mn0);
        float c1 = exp2f(m1 - mn1);
        m0 = mn0; m1 = mn1;
        float rs0 = 0.f, rs1 = 0.f;
#pragma unroll
        for (int nf = 0; nf < 8; nf++) {
            s[nf][0] = exp2f(s[nf][0] - m0); rs0 += s[nf][0];
            s[nf][1] = exp2f(s[nf][1] - m0); rs0 += s[nf][1];
            s[nf][2] = exp2f(s[nf][2] - m1); rs1 += s[nf][2];
            s[nf][3] = exp2f(s[nf][3] - m1); rs1 += s[nf][3];
        }
        rs0 += __shfl_xor_sync(0xffffffffu, rs0, 1);
        rs0 += __shfl_xor_sync(0xffffffffu, rs0, 2);
        rs1 += __shfl_xor_sync(0xffffffffu, rs1, 1);
        rs1 += __shfl_xor_sync(0xffffffffu, rs1, 2);
        l0 = l0 * c0 + rs0;
        l1 = l1 * c1 + rs1;
#pragma unroll
        for (int i = 0; i < 16; i++) {
            oa[i][0] *= c0; oa[i][1] *= c0;
            oa[i][2] *= c1; oa[i][3] *= c1;
        }

        asm volatile("cp.async.wait_group 1;");
        __syncthreads();

#pragma unroll
        for (int kf2 = 0; kf2 < 4; kf2++) {
            uint32_t pah[4], pal[4];
            pah[0] = pack_hl(s[2 * kf2][0], s[2 * kf2][1], pal[0]);
            pah[1] = pack_hl(s[2 * kf2][2], s[2 * kf2][3], pal[1]);
            pah[2] = pack_hl(s[2 * kf2 + 1][0], s[2 * kf2 + 1][1], pal[2]);
            pah[3] = pack_hl(s[2 * kf2 + 1][2], s[2 * kf2 + 1][3], pal[3]);
#pragma unroll
            for (int np = 0; np < 8; np++) {
                uint32_t voff = (uint32_t)((np * 16 + brow) * VLDT + kf2 * 32 + bch * 16);
                uint32_t vh[4], vl[4];
                ldsm_x4(sb + FV + voff, vh[0], vh[1], vh[2], vh[3]);
                ldsm_x4(sb + FV + 18432 + voff, vl[0], vl[1], vl[2], vl[3]);
                mma_bf16(oa[np * 2], pah, vh);
                mma_bf16(oa[np * 2], pah, vl);
                mma_bf16(oa[np * 2], pal, vh);
                mma_bf16(oa[np * 2 + 1], pah, vh + 2);
                mma_bf16(oa[np * 2 + 1], pah, vl + 2);
                mma_bf16(oa[np * 2 + 1], pal, vh + 2);
            }
        }
        __syncthreads();
    }

    // epilogue: normalize, write fp16 attn (operand for fp16x2 O-proj)
    const float inv0 = 1.0f / l0;
    const float inv1 = 1.0f / l1;
#pragma unroll
    for (int nf2 = 0; nf2 < 16; nf2++) {
        int col = h * HD + nf2 * 8 + (lane & 3) * 2;
        __half2 p0 = __floats2half2_rn(oa[nf2][0] * inv0, oa[nf2][1] * inv0);
        __half2 p1 = __floats2half2_rn(oa[nf2][2] * inv1, oa[nf2][3] * inv1);
        *(uint32_t*)&o1[(size_t)r0g * HID + col] = *(uint32_t*)&p0;
        *(uint32_t*)&o1[(size_t)r1g * HID + col] = *(uint32_t*)&p1;
    }
}

// ---------------------------------------------------------------------------
// launcher
// ---------------------------------------------------------------------------
extern "C" void kernel_launch(void* const* d_in, const int* in_sizes, int n_in,
                              void* d_out, int out_size) {
    const float* hidden = (const float*)d_in[0];
    const float* cosb = (const float*)d_in[2];
    const float* sinb = (const float*)d_in[3];
    const float* wq = (const float*)d_in[4];
    const float* wk = (const float*)d_in[5];
    const float* wv = (const float*)d_in[6];
    const float* wo = (const float*)d_in[7];
    float* out = (float*)d_out;

    float* v;
    cudaGetSymbolAddress((void**)&v, g_v);
    __half* at1;
    cudaGetSymbolAddress((void**)&at1, g_at1);
    __nv_bfloat16 *qr_hi, *qr_lo, *kr_hi, *kr_lo, *vt_hi, *vt_lo;
    cudaGetSymbolAddress((void**)&qr_hi, g_qr_hi);
    cudaGetSymbolAddress((void**)&qr_lo, g_qr_lo);
    cudaGetSymbolAddress((void**)&kr_hi, g_kr_hi);
    cudaGetSymbolAddress((void**)&kr_lo, g_kr_lo);
    cudaGetSymbolAddress((void**)&vt_hi, g_vt_hi);
    cudaGetSymbolAddress((void**)&vt_lo, g_vt_lo);

    // fused split (hidden fp16 single; weights fp16 pairs)
    split_all<<<SPLIT_GRID, 256>>>(hidden, wq, wk, wv, wo);

    cudaFuncSetAttribute(gemm_qkv, cudaFuncAttributeMaxDynamicSharedMemorySize,
                         GEMM_SMEM);
    cudaFuncSetAttribute(gemm_o, cudaFuncAttributeMaxDynamicSharedMemorySize,
                         GEMM_SMEM);

    // fused QKV projection (fp16x2, RoPE fused for Q/K)
    gemm_qkv<<<dim3(S_LEN / 256, 48), 256, GEMM_SMEM>>>(cosb, sinb);

    // V transpose + split (bf16 hi/lo for flash)
    transpose_split<<<dim3(S_LEN / 32, KVDIM / 32), dim3(32, 8)>>>(v, vt_hi, vt_lo);

    // flash attention (bf16x3), writes fp16 attn
    cudaFuncSetAttribute(flash_tc, cudaFuncAttributeMaxDynamicSharedMemorySize,
                         FLASH_SMEM);
    flash_tc<<<dim3(32, 32), 128, FLASH_SMEM>>>(qr_hi, qr_lo, kr_hi, kr_lo,
                                                vt_hi, vt_lo, at1);

    // output projection (fp16x2)
    gemm_o<<<dim3(S_LEN / 256, HID / 128), 256, GEMM_SMEM>>>(out);
}

// round 13
// speedup vs baseline: 3.4048x; 1.0156x over previous
#include <cuda_runtime.h>
#include <cuda_bf16.h>
#include <cuda_fp16.h>
#include <stdint.h>

// ---------------------------------------------------------------------------
// LlamaAttention: S=2048, HID=4096, NH=32, NKV=8, D=128
// Projections: fp16x2 warp-MMA GEMM, 3-stage cp.async.
// Flash: QK bf16x3, PV fp16x2 (P single fp16, V hi+lo), 2 CTA/SM.
// RoPE fused in QKV epilogue. HMMA-only path (tcgen05/IMMA unusable).
// ---------------------------------------------------------------------------

#define S_LEN 2048
#define HID   4096
#define NH    32
#define NKV   8
#define HD    128
#define KVDIM (NKV * HD)   // 1024
#define KDIM  4096

// fp32 scratch (V only)
__device__ float g_v[S_LEN * KVDIM];

// fp16 GEMM operands
__device__ __half g_h1[S_LEN * KDIM];
__device__ __half g_wq1[HID * KDIM],   g_wq2[HID * KDIM];
__device__ __half g_wk1[KVDIM * KDIM], g_wk2[KVDIM * KDIM];
__device__ __half g_wv1[KVDIM * KDIM], g_wv2[KVDIM * KDIM];
__device__ __half g_wo1[HID * KDIM],   g_wo2[HID * KDIM];
__device__ __half g_at1[S_LEN * KDIM];

// attention operands: Q/K bf16 hi/lo, V fp16 hi/lo (transposed)
__device__ __nv_bfloat16 g_qr_hi[S_LEN * HID];
__device__ __nv_bfloat16 g_qr_lo[S_LEN * HID];
__device__ __nv_bfloat16 g_kr_hi[S_LEN * KVDIM];
__device__ __nv_bfloat16 g_kr_lo[S_LEN * KVDIM];
__device__ __half g_vt1[KVDIM * S_LEN];
__device__ __half g_vt2[KVDIM * S_LEN];

__device__ __forceinline__ uint32_t pack_hl(float f0, float f1, uint32_t& lo) {
    __nv_bfloat162 h = __floats2bfloat162_rn(f0, f1);
    float r0 = f0 - __bfloat162float(h.x);
    float r1 = f1 - __bfloat162float(h.y);
    __nv_bfloat162 l = __floats2bfloat162_rn(r0, r1);
    lo = *(uint32_t*)&l;
    return *(uint32_t*)&h;
}

// ---------------------------------------------------------------------------
// fused split
// ---------------------------------------------------------------------------
#define N_HID (S_LEN * KDIM)
#define N_WQ  (HID * KDIM)
#define N_WKV (KVDIM * KDIM)
#define SEG0  N_HID
#define SEG1  (SEG0 + N_WQ)
#define SEG2  (SEG1 + N_WKV)
#define SEG3  (SEG2 + N_WKV)
#define SEG4  (SEG3 + N_WQ)
#define SPLIT_GRID (SEG4 / (8 * 256))

__device__ __forceinline__ void split8_pair(const float* src, __half* h1,
                                            __half* h2, int off) {
    float4 f[2];
    f[0] = *(const float4*)(src + off);
    f[1] = *(const float4*)(src + off + 4);
    __half2 o1[4], o2[4];
#pragma unroll
    for (int j = 0; j < 2; j++) {
        const float v[4] = {f[j].x, f[j].y, f[j].z, f[j].w};
#pragma unroll
        for (int p = 0; p < 2; p++) {
            __half a = __float2half_rn(v[p * 2]);
            __half b = __float2half_rn(v[p * 2 + 1]);
            __half ra = __float2half_rn(v[p * 2] - __half2float(a));
            __half rb = __float2half_rn(v[p * 2 + 1] - __half2float(b));
            o1[j * 2 + p] = __halves2half2(a, b);
            o2[j * 2 + p] = __halves2half2(ra, rb);
        }
    }
    *(uint4*)(h1 + off) = *(uint4*)o1;
    *(uint4*)(h2 + off) = *(uint4*)o2;
}

__device__ __forceinline__ void split8_single(const float* src, __half* h1, int off) {
    float4 f[2];
    f[0] = *(const float4*)(src + off);
    f[1] = *(const float4*)(src + off + 4);
    __half2 o1[4];
    o1[0] = __floats2half2_rn(f[0].x, f[0].y);
    o1[1] = __floats2half2_rn(f[0].z, f[0].w);
    o1[2] = __floats2half2_rn(f[1].x, f[1].y);
    o1[3] = __floats2half2_rn(f[1].z, f[1].w);
    *(uint4*)(h1 + off) = *(uint4*)o1;
}

__global__ void split_all(const float* __restrict__ hidden,
                          const float* __restrict__ wq,
                          const float* __restrict__ wk,
                          const float* __restrict__ wv,
                          const float* __restrict__ wo) {
    int g = (blockIdx.x * blockDim.x + threadIdx.x) * 8;
    if (g < SEG0)      split8_single(hidden, g_h1, g);
    else if (g < SEG1) split8_pair(wq, g_wq1, g_wq2, g - SEG0);
    else if (g < SEG2) split8_pair(wk, g_wk1, g_wk2, g - SEG1);
    else if (g < SEG3) split8_pair(wv, g_wv1, g_wv2, g - SEG2);
    else               split8_pair(wo, g_wo1, g_wo2, g - SEG3);
}

// ---------------------------------------------------------------------------
// warp-MMA primitives
// ---------------------------------------------------------------------------
__device__ __forceinline__ void ldsm_x4(uint32_t addr, uint32_t& r0, uint32_t& r1,
                                        uint32_t& r2, uint32_t& r3) {
    asm volatile("ldmatrix.sync.aligned.m8n8.x4.shared.b16 {%0,%1,%2,%3}, [%4];"
                 : "=r"(r0), "=r"(r1), "=r"(r2), "=r"(r3) : "r"(addr));
}

__device__ __forceinline__ void mma_bf16(float* c, const uint32_t* a, const uint32_t* b) {
    asm volatile(
        "mma.sync.aligned.m16n8k16.row.col.f32.bf16.bf16.f32 "
        "{%0,%1,%2,%3},{%4,%5,%6,%7},{%8,%9},{%0,%1,%2,%3};"
        : "+f"(c[0]), "+f"(c[1]), "+f"(c[2]), "+f"(c[3])
        : "r"(a[0]), "r"(a[1]), "r"(a[2]), "r"(a[3]), "r"(b[0]), "r"(b[1]));
}

__device__ __forceinline__ void mma_f16(float* c, const uint32_t* a, const uint32_t* b) {
    asm volatile(
        "mma.sync.aligned.m16n8k16.row.col.f32.f16.f16.f32 "
        "{%0,%1,%2,%3},{%4,%5,%6,%7},{%8,%9},{%0,%1,%2,%3};"
        : "+f"(c[0]), "+f"(c[1]), "+f"(c[2]), "+f"(c[3])
        : "r"(a[0]), "r"(a[1]), "r"(a[2]), "r"(a[3]), "r"(b[0]), "r"(b[1]));
}

// ---------------------------------------------------------------------------
// fp16x2 GEMM body: C = A1·B1 + A1·B2. Block 256x128, warp 64x64, BK=64,
// 256 threads, 3-stage cp.async, 144B-padded rows.
// ---------------------------------------------------------------------------
#define GBK  64
#define LDT  144
#define A_T  (256 * LDT)                 // 36864
#define B_T  (128 * LDT)                 // 18432
#define STG  (A_T + 2 * B_T)             // 73728
#define GEMM_SMEM (3 * STG)              // 221184

__device__ __forceinline__ void gemm_body_f16(
    const __half* __restrict__ A1,
    const __half* __restrict__ B1, const __half* __restrict__ B2,
    float* __restrict__ Cf, __nv_bfloat16* __restrict__ Chi,
    __nv_bfloat16* __restrict__ Clo,
    const float* __restrict__ cosb, const float* __restrict__ sinb,
    int mode, int N, int bm, int bn, char* smem) {
    const int tid = threadIdx.x;
    const int lane = tid & 31;
    const int warp = tid >> 5;
    const int wr = warp >> 1;
    const int wc = warp & 1;
    uint32_t sbase = (uint32_t)__cvta_generic_to_shared(smem);

    float acc[4][8][4];
#pragma unroll
    for (int mi = 0; mi < 4; mi++)
#pragma unroll
        for (int ni = 0; ni < 8; ni++)
#pragma unroll
            for (int t = 0; t < 4; t++) acc[mi][ni][t] = 0.f;

    auto load_stage = [&](int s, int it) {
        const int kbase = it * GBK;
        uint32_t dst0 = sbase + s * STG;
#pragma unroll
        for (int i = 0; i < 16; i++) {
            int c = tid + i * 256;
            const __half* gsrc;
            uint32_t daddr;
            if (c < 2048) {
                int row = c >> 3;
                int ch = c & 7;
                gsrc = A1 + (size_t)(bm + row) * KDIM + kbase + ch * 8;
                daddr = dst0 + row * LDT + ch * 16;
            } else {
                int cb = c - 2048;
                int mat = cb >> 10;
                int idx = cb & 1023;
                int row = idx >> 3;
                int ch = idx & 7;
                gsrc = (mat ? B2 : B1) + (size_t)(bn + row) * KDIM + kbase + ch * 8;
                daddr = dst0 + A_T + mat * B_T + row * LDT + ch * 16;
            }
            asm volatile("cp.async.cg.shared.global [%0], [%1], 16;"
                         :: "r"(daddr), "l"(gsrc));
        }
        asm volatile("cp.async.commit_group;");
    };

    const int NIT = KDIM / GBK;   // 64
    load_stage(0, 0);
    load_stage(1, 1);

    const int brow = (lane & 7) + ((lane >> 4) << 3);
    const int bch = (lane >> 3) & 1;

    for (int it = 0; it < NIT; it++) {
        asm volatile("cp.async.wait_group 1;");
        __syncthreads();
        // prefetch stage (it+2): overwrites stage used by compute(it-1),
        // which all threads finished before the barrier above.
        if (it + 2 < NIT) load_stage((it + 2) % 3, it + 2);
        else              asm volatile("cp.async.commit_group;");

        uint32_t sa = sbase + (it % 3) * STG;
#pragma unroll
        for (int ks = 0; ks < 4; ks++) {
            uint32_t af[4][4];
#pragma unroll
            for (int mi = 0; mi < 4; mi++) {
                uint32_t off = (uint32_t)((wr * 64 + mi * 16 + (lane & 15)) * LDT +
                                          ks * 32 + ((lane >> 4) & 1) * 16);
                ldsm_x4(sa + off, af[mi][0], af[mi][1], af[mi][2], af[mi][3]);
            }
#pragma unroll
            for (int half = 0; half < 2; half++) {
                uint32_t b1[4][2], b2[4][2];
#pragma unroll
                for (int np = 0; np < 2; np++) {
                    uint32_t off = (uint32_t)((wc * 64 + half * 32 + np * 16 + brow) * LDT +
                                              ks * 32 + bch * 16);
                    uint32_t r0, r1, r2, r3;
                    ldsm_x4(sa + A_T + off, r0, r1, r2, r3);
                    b1[np * 2][0] = r0; b1[np * 2][1] = r1;
                    b1[np * 2 + 1][0] = r2; b1[np * 2 + 1][1] = r3;
                    ldsm_x4(sa + A_T + B_T + off, r0, r1, r2, r3);
                    b2[np * 2][0] = r0; b2[np * 2][1] = r1;
                    b2[np * 2 + 1][0] = r2; b2[np * 2 + 1][1] = r3;
                }
#pragma unroll
                for (int mi = 0; mi < 4; mi++)
#pragma unroll
                    for (int nf = 0; nf < 4; nf++) {
                        float* a = acc[mi][half * 4 + nf];
                        mma_f16(a, af[mi], b1[nf]);
                        mma_f16(a, af[mi], b2[nf]);
                    }
            }
        }
    }

    if (mode == 0) {
#pragma unroll
        for (int mi = 0; mi < 4; mi++) {
            const int r0 = bm + wr * 64 + mi * 16 + (lane >> 2);
#pragma unroll
            for (int ni = 0; ni < 8; ni++) {
                const int col = bn + wc * 64 + ni * 8 + (lane & 3) * 2;
                *(float2*)&Cf[(size_t)r0 * N + col] = make_float2(acc[mi][ni][0], acc[mi][ni][1]);
                *(float2*)&Cf[(size_t)(r0 + 8) * N + col] = make_float2(acc[mi][ni][2], acc[mi][ni][3]);
            }
        }
    } else {
#pragma unroll
        for (int mi = 0; mi < 4; mi++) {
            const int r0 = bm + wr * 64 + mi * 16 + (lane >> 2);
            const int r1 = r0 + 8;
#pragma unroll
            for (int ni = 0; ni < 8; ni++) {
                const int col = bn + wc * 64 + ni * 8 + (lane & 3) * 2;
                const int i = (col & 127) >> 1;
                float c0 = cosb[r0 * 64 + i], s0 = sinb[r0 * 64 + i];
                float c1 = cosb[r1 * 64 + i], s1 = sinb[r1 * 64 + i];
                float a0 = acc[mi][ni][0], b0 = acc[mi][ni][1];
                float a1 = acc[mi][ni][2], b1 = acc[mi][ni][3];
                float x0 = a0 * c0 - b0 * s0, y0 = a0 * s0 + b0 * c0;
                float x1 = a1 * c1 - b1 * s1, y1 = a1 * s1 + b1 * c1;
                uint32_t lo32, hi32;
                hi32 = pack_hl(x0, y0, lo32);
                *(uint32_t*)&Chi[(size_t)r0 * N + col] = hi32;
                *(uint32_t*)&Clo[(size_t)r0 * N + col] = lo32;
                hi32 = pack_hl(x1, y1, lo32);
                *(uint32_t*)&Chi[(size_t)r1 * N + col] = hi32;
                *(uint32_t*)&Clo[(size_t)r1 * N + col] = lo32;
            }
        }
    }
}

__global__ __launch_bounds__(256, 1) void gemm_qkv(const float* __restrict__ cosb,
                                                   const float* __restrict__ sinb) {
    extern __shared__ char smem[];
    const int y = blockIdx.y;
    const int bm = blockIdx.x * 256;
    if (y < 32) {
        gemm_body_f16(g_h1, g_wq1, g_wq2, nullptr, g_qr_hi, g_qr_lo,
                      cosb, sinb, 1, HID, bm, y * 128, smem);
    } else if (y < 40) {
        gemm_body_f16(g_h1, g_wk1, g_wk2, nullptr, g_kr_hi, g_kr_lo,
                      cosb, sinb, 1, KVDIM, bm, (y - 32) * 128, smem);
    } else {
        gemm_body_f16(g_h1, g_wv1, g_wv2, g_v, nullptr, nullptr,
                      nullptr, nullptr, 0, KVDIM, bm, (y - 40) * 128, smem);
    }
}

__global__ __launch_bounds__(256, 1) void gemm_o(float* __restrict__ out) {
    extern __shared__ char smem[];
    gemm_body_f16(g_at1, g_wo1, g_wo2, out, nullptr, nullptr,
                  nullptr, nullptr, 0, HID, blockIdx.x * 256, blockIdx.y * 128, smem);
}

// ---------------------------------------------------------------------------
// transpose + split: v[S,1024] fp32 -> vT fp16 hi/lo [1024, S]
// ---------------------------------------------------------------------------
__global__ void transpose_split(const float* __restrict__ v,
                                __half* __restrict__ th,
                                __half* __restrict__ tl) {
    __shared__ float tile[32][33];
    const int bs = blockIdx.x * 32;
    const int bd = blockIdx.y * 32;
    const int tx = threadIdx.x;
    const int ty = threadIdx.y;
#pragma unroll
    for (int i = 0; i < 4; i++) {
        int sy = ty * 4 + i;
        tile[sy][tx] = v[(size_t)(bs + sy) * KVDIM + bd + tx];
    }
    __syncthreads();
#pragma unroll
    for (int i = 0; i < 4; i++) {
        int dy = ty * 4 + i;
        float val = tile[tx][dy];
        __half h = __float2half_rn(val);
        __half l = __float2half_rn(val - __half2float(h));
        th[(size_t)(bd + dy) * S_LEN + bs + tx] = h;
        tl[(size_t)(bd + dy) * S_LEN + bs + tx] = l;
    }
}

// ---------------------------------------------------------------------------
// Flash attention: QK bf16x3, PV fp16x2. BQ=64, 128 thr, Q in registers.
// K double-buffered / V pipelined. 106.5KB -> 2 CTA/SM. exp2 softmax.
// Writes fp16 attn. Grid (32 qb reversed, 32 h).
// ---------------------------------------------------------------------------
#define QLDT 272
#define VLDT 144
#define FK0  0
#define FK1  34816
#define FV   69632
#define FLASH_SMEM (FV + 36864)   // 106496

__global__ __launch_bounds__(128, 2) void flash_tc(
    const __nv_bfloat16* __restrict__ qh, const __nv_bfloat16* __restrict__ ql,
    const __nv_bfloat16* __restrict__ kh, const __nv_bfloat16* __restrict__ kl,
    const __half* __restrict__ vt1, const __half* __restrict__ vt2,
    __half* __restrict__ o1) {
    extern __shared__ char sm[];
    const int qb = (int)gridDim.x - 1 - (int)blockIdx.x;
    const int h  = blockIdx.y;
    const int kvh = h >> 2;
    const int tid = threadIdx.x;
    const int lane = tid & 31;
    const int w = tid >> 5;
    const int q0 = qb * 64;
    const float scale2 = 0.12751744685137577f;   // (1/sqrt(128)) * log2(e)
    uint32_t sb = (uint32_t)__cvta_generic_to_shared(sm);

    const int brow = (lane & 7) + ((lane >> 4) << 3);
    const int bch = (lane >> 3) & 1;

    for (int i = tid; i < 2048; i += 128) {
        int mat = i >> 10;
        int idx = i & 1023;
        int r = idx >> 4;
        int c = idx & 15;
        const __nv_bfloat16* src = (mat ? ql : qh) + (size_t)(q0 + r) * HID + h * HD + c * 8;
        *(uint4*)(sm + FK1 + mat * 17408 + r * QLDT + c * 16) = *(const uint4*)src;
    }
    __syncthreads();
    uint32_t qfh[8][4], qfl[8][4];
#pragma unroll
    for (int kf = 0; kf < 8; kf++) {
        uint32_t aoff = (uint32_t)((w * 16 + (lane & 15)) * QLDT + kf * 32 + (lane >> 4) * 16);
        ldsm_x4(sb + FK1 + aoff, qfh[kf][0], qfh[kf][1], qfh[kf][2], qfh[kf][3]);
        ldsm_x4(sb + FK1 + 17408 + aoff, qfl[kf][0], qfl[kf][1], qfl[kf][2], qfl[kf][3]);
    }
    __syncthreads();

    auto loadK = [&](int kb) {
        const int k0 = kb * 64;
        uint32_t kdst = sb + ((kb & 1) ? FK1 : FK0);
#pragma unroll
        for (int i0 = 0; i0 < 16; i0++) {
            int i = tid + i0 * 128;
            int mat = i >> 10;
            int idx = i & 1023;
            int r = idx >> 4;
            int c = idx & 15;
            const void* src = (mat ? kl : kh) + (size_t)(k0 + r) * KVDIM + kvh * HD + c * 8;
            asm volatile("cp.async.cg.shared.global [%0], [%1], 16;"
                         :: "r"(kdst + mat * 17408 + r * QLDT + c * 16), "l"(src));
        }
        asm volatile("cp.async.commit_group;");
    };
    auto loadV = [&](int kb) {
        const int k0 = kb * 64;
        uint32_t vdst = sb + FV;
#pragma unroll
        for (int i0 = 0; i0 < 16; i0++) {
            int i = tid + i0 * 128;
            int mat = i >> 10;
            int idx = i & 1023;
            int r = idx >> 3;
            int c = idx & 7;
            const void* src = (mat ? vt2 : vt1) + (size_t)(kvh * HD + r) * S_LEN + k0 + c * 8;
            asm volatile("cp.async.cg.shared.global [%0], [%1], 16;"
                         :: "r"(vdst + mat * 18432 + r * VLDT + c * 16), "l"(src));
        }
        asm volatile("cp.async.commit_group;");
    };

    float m0 = -1e30f, m1 = -1e30f, l0 = 0.f, l1 = 0.f;
    float oa[16][4];
#pragma unroll
    for (int i = 0; i < 16; i++)
#pragma unroll
        for (int t = 0; t < 4; t++) oa[i][t] = 0.f;

    const int r0g = q0 + w * 16 + (lane >> 2);
    const int r1g = r0g + 8;

    loadK(0);

    for (int kb = 0; kb <= qb; kb++) {
        const int k0 = kb * 64;
        loadV(kb);
        if (kb < qb) loadK(kb + 1);
        else         asm volatile("cp.async.commit_group;");
        asm volatile("cp.async.wait_group 2;");
        __syncthreads();

        const uint32_t kbase = sb + ((kb & 1) ? FK1 : FK0);

        float s[8][4];
#pragma unroll
        for (int nf = 0; nf < 8; nf++)
#pragma unroll
            for (int t = 0; t < 4; t++) s[nf][t] = 0.f;

#pragma unroll
        for (int kf = 0; kf < 8; kf++) {
#pragma unroll
            for (int np = 0; np < 4; np++) {
                uint32_t boff = (uint32_t)((np * 16 + brow) * QLDT + kf * 32 + bch * 16);
                uint32_t bh[4], bl[4];
                ldsm_x4(kbase + boff, bh[0], bh[1], bh[2], bh[3]);
                ldsm_x4(kbase + 17408 + boff, bl[0], bl[1], bl[2], bl[3]);
                mma_bf16(s[np * 2], qfh[kf], bh);
                mma_bf16(s[np * 2], qfh[kf], bl);
                mma_bf16(s[np * 2], qfl[kf], bh);
                mma_bf16(s[np * 2 + 1], qfh[kf], bh + 2);
                mma_bf16(s[np * 2 + 1], qfh[kf], bl + 2);
                mma_bf16(s[np * 2 + 1], qfl[kf], bh + 2);
            }
        }

#pragma unroll
        for (int nf = 0; nf < 8; nf++)
#pragma unroll
            for (int t = 0; t < 4; t++) s[nf][t] *= scale2;
        if (kb == qb) {
#pragma unroll
            for (int nf = 0; nf < 8; nf++) {
                int cg = k0 + nf * 8 + (lane & 3) * 2;
                if (cg > r0g)     s[nf][0] = -1e30f;
                if (cg + 1 > r0g) s[nf][1] = -1e30f;
                if (cg > r1g)     s[nf][2] = -1e30f;
                if (cg + 1 > r1g) s[nf][3] = -1e30f;
            }
        }

        float mx0 = -1e30f, mx1 = -1e30f;
#pragma unroll
        for (int nf = 0; nf < 8; nf++) {
            mx0 = fmaxf(mx0, fmaxf(s[nf][0], s[nf][1]));
            mx1 = fmaxf(mx1, fmaxf(s[nf][2], s[nf][3]));
        }
        mx0 = fmaxf(mx0, __shfl_xor_sync(0xffffffffu, mx0, 1));
        mx0 = fmaxf(mx0, __shfl_xor_sync(0xffffffffu, mx0, 2));
        mx1 = fmaxf(mx1, __shfl_xor_sync(0xffffffffu, mx1, 1));
        mx1 = fmaxf(mx1, __shfl_xor_sync(0xffffffffu, mx1, 2));
        float mn0 = fmaxf(m0, mx0);
        float mn1 = fmaxf(m1, mx1);
        float c0 = exp2f(m0 - mn0);
        float c1 = exp2f(m1 - mn1);
        m0 = mn0; m1 = mn1;
        float rs0 = 0.f, rs1 = 0.f;
#pragma unroll
        for (int nf = 0; nf < 8; nf++) {
            s[nf][0] = exp2f(s[nf][0] - m0); rs0 += s[nf][0];
            s[nf][1] = exp2f(s[nf][1] - m0); rs0 += s[nf][1];
            s[nf][2] = exp2f(s[nf][2] - m1); rs1 += s[nf][2];
            s[nf][3] = exp2f(s[nf][3] - m1); rs1 += s[nf][3];
        }
        rs0 += __shfl_xor_sync(0xffffffffu, rs0, 1);
        rs0 += __shfl_xor_sync(0xffffffffu, rs0, 2);
        rs1 += __shfl_xor_sync(0xffffffffu, rs1, 1);
        rs1 += __shfl_xor_sync(0xffffffffu, rs1, 2);
        l0 = l0 * c0 + rs0;
        l1 = l1 * c1 + rs1;
#pragma unroll
        for (int i = 0; i < 16; i++) {
            oa[i][0] *= c0; oa[i][1] *= c0;
            oa[i][2] *= c1; oa[i][3] *= c1;
        }

        asm volatile("cp.async.wait_group 1;");
        __syncthreads();

        // O += P V (P single fp16, V hi+lo fp16: 4 MMAs per np)
#pragma unroll
        for (int kf2 = 0; kf2 < 4; kf2++) {
            uint32_t pah[4];
            {
                __half2 t0 = __floats2half2_rn(s[2 * kf2][0], s[2 * kf2][1]);
                __half2 t1 = __floats2half2_rn(s[2 * kf2][2], s[2 * kf2][3]);
                __half2 t2 = __floats2half2_rn(s[2 * kf2 + 1][0], s[2 * kf2 + 1][1]);
                __half2 t3 = __floats2half2_rn(s[2 * kf2 + 1][2], s[2 * kf2 + 1][3]);
                pah[0] = *(uint32_t*)&t0;
                pah[1] = *(uint32_t*)&t1;
                pah[2] = *(uint32_t*)&t2;
                pah[3] = *(uint32_t*)&t3;
            }
#pragma unroll
            for (int np = 0; np < 8; np++) {
                uint32_t voff = (uint32_t)((np * 16 + brow) * VLDT + kf2 * 32 + bch * 16);
                uint32_t v1[4], v2[4];
                ldsm_x4(sb + FV + voff, v1[0], v1[1], v1[2], v1[3]);
                ldsm_x4(sb + FV + 18432 + voff, v2[0], v2[1], v2[2], v2[3]);
                mma_f16(oa[np * 2], pah, v1);
                mma_f16(oa[np * 2], pah, v2);
                mma_f16(oa[np * 2 + 1], pah, v1 + 2);
                mma_f16(oa[np * 2 + 1], pah, v2 + 2);
            }
        }
        __syncthreads();
    }

    const float inv0 = 1.0f / l0;
    const float inv1 = 1.0f / l1;
#pragma unroll
    for (int nf2 = 0; nf2 < 16; nf2++) {
        int col = h * HD + nf2 * 8 + (lane & 3) * 2;
        __half2 p0 = __floats2half2_rn(oa[nf2][0] * inv0, oa[nf2][1] * inv0);
        __half2 p1 = __floats2half2_rn(oa[nf2][2] * inv1, oa[nf2][3] * inv1);
        *(uint32_t*)&o1[(size_t)r0g * HID + col] = *(uint32_t*)&p0;
        *(uint32_t*)&o1[(size_t)r1g * HID + col] = *(uint32_t*)&p1;
    }
}

// ---------------------------------------------------------------------------
// launcher
// ---------------------------------------------------------------------------
extern "C" void kernel_launch(void* const* d_in, const int* in_sizes, int n_in,
                              void* d_out, int out_size) {
    const float* hidden = (const float*)d_in[0];
    const float* cosb = (const float*)d_in[2];
    const float* sinb = (const float*)d_in[3];
    const float* wq = (const float*)d_in[4];
    const float* wk = (const float*)d_in[5];
    const float* wv = (const float*)d_in[6];
    const float* wo = (const float*)d_in[7];
    float* out = (float*)d_out;

    float* v;
    cudaGetSymbolAddress((void**)&v, g_v);
    __half *at1, *vt1, *vt2;
    cudaGetSymbolAddress((void**)&at1, g_at1);
    cudaGetSymbolAddress((void**)&vt1, g_vt1);
    cudaGetSymbolAddress((void**)&vt2, g_vt2);
    __nv_bfloat16 *qr_hi, *qr_lo, *kr_hi, *kr_lo;
    cudaGetSymbolAddress((void**)&qr_hi, g_qr_hi);
    cudaGetSymbolAddress((void**)&qr_lo, g_qr_lo);
    cudaGetSymbolAddress((void**)&kr_hi, g_kr_hi);
    cudaGetSymbolAddress((void**)&kr_lo, g_kr_lo);

    split_all<<<SPLIT_GRID, 256>>>(hidden, wq, wk, wv, wo);

    cudaFuncSetAttribute(gemm_qkv, cudaFuncAttributeMaxDynamicSharedMemorySize,
                         GEMM_SMEM);
    cudaFuncSetAttribute(gemm_o, cudaFuncAttributeMaxDynamicSharedMemorySize,
                         GEMM_SMEM);

    gemm_qkv<<<dim3(S_LEN / 256, 48), 256, GEMM_SMEM>>>(cosb, sinb);

    transpose_split<<<dim3(S_LEN / 32, KVDIM / 32), dim3(32, 8)>>>(v, vt1, vt2);

    cudaFuncSetAttribute(flash_tc, cudaFuncAttributeMaxDynamicSharedMemorySize,
                         FLASH_SMEM);
    flash_tc<<<dim3(32, 32), 128, FLASH_SMEM>>>(qr_hi, qr_lo, kr_hi, kr_lo,
                                                vt1, vt2, at1);

    gemm_o<<<dim3(S_LEN / 256, HID / 128), 256, GEMM_SMEM>>>(out);
}

// round 14
// speedup vs baseline: 3.6571x; 1.0741x over previous
#include <cuda_runtime.h>
#include <cuda_bf16.h>
#include <cuda_fp16.h>
#include <stdint.h>

// ---------------------------------------------------------------------------
// LlamaAttention: S=2048, HID=4096, NH=32, NKV=8, D=128
// Projections: fp16x2 warp-MMA GEMM (A single, B hi+lo), 3-stage cp.async.
// Flash: QK fp16x2 (Q single, K hi+lo), PV fp16x2 (P single, V hi+lo).
// RoPE fused in QKV epilogue. HMMA-only path.
// ---------------------------------------------------------------------------

#define S_LEN 2048
#define HID   4096
#define NH    32
#define NKV   8
#define HD    128
#define KVDIM (NKV * HD)   // 1024
#define KDIM  4096

// fp32 scratch (V only)
__device__ float g_v[S_LEN * KVDIM];

// fp16 GEMM operands
__device__ __half g_h1[S_LEN * KDIM];
__device__ __half g_wq1[HID * KDIM],   g_wq2[HID * KDIM];
__device__ __half g_wk1[KVDIM * KDIM], g_wk2[KVDIM * KDIM];
__device__ __half g_wv1[KVDIM * KDIM], g_wv2[KVDIM * KDIM];
__device__ __half g_wo1[HID * KDIM],   g_wo2[HID * KDIM];
__device__ __half g_at1[S_LEN * KDIM];

// attention operands: Q single fp16, K fp16 hi/lo, V fp16 hi/lo (transposed)
__device__ __half g_q1[S_LEN * HID];
__device__ __half g_k1[S_LEN * KVDIM];
__device__ __half g_k2[S_LEN * KVDIM];
__device__ __half g_vt1[KVDIM * S_LEN];
__device__ __half g_vt2[KVDIM * S_LEN];

__device__ __forceinline__ uint32_t pack_hl_f16(float f0, float f1, uint32_t& lo) {
    __half2 h = __floats2half2_rn(f0, f1);
    float r0 = f0 - __half2float(h.x);
    float r1 = f1 - __half2float(h.y);
    __half2 l = __floats2half2_rn(r0, r1);
    lo = *(uint32_t*)&l;
    return *(uint32_t*)&h;
}

// ---------------------------------------------------------------------------
// fused split
// ---------------------------------------------------------------------------
#define N_HID (S_LEN * KDIM)
#define N_WQ  (HID * KDIM)
#define N_WKV (KVDIM * KDIM)
#define SEG0  N_HID
#define SEG1  (SEG0 + N_WQ)
#define SEG2  (SEG1 + N_WKV)
#define SEG3  (SEG2 + N_WKV)
#define SEG4  (SEG3 + N_WQ)
#define SPLIT_GRID (SEG4 / (8 * 256))

__device__ __forceinline__ void split8_pair(const float* src, __half* h1,
                                            __half* h2, int off) {
    float4 f[2];
    f[0] = *(const float4*)(src + off);
    f[1] = *(const float4*)(src + off + 4);
    __half2 o1[4], o2[4];
#pragma unroll
    for (int j = 0; j < 2; j++) {
        const float v[4] = {f[j].x, f[j].y, f[j].z, f[j].w};
#pragma unroll
        for (int p = 0; p < 2; p++) {
            __half a = __float2half_rn(v[p * 2]);
            __half b = __float2half_rn(v[p * 2 + 1]);
            __half ra = __float2half_rn(v[p * 2] - __half2float(a));
            __half rb = __float2half_rn(v[p * 2 + 1] - __half2float(b));
            o1[j * 2 + p] = __halves2half2(a, b);
            o2[j * 2 + p] = __halves2half2(ra, rb);
        }
    }
    *(uint4*)(h1 + off) = *(uint4*)o1;
    *(uint4*)(h2 + off) = *(uint4*)o2;
}

__device__ __forceinline__ void split8_single(const float* src, __half* h1, int off) {
    float4 f[2];
    f[0] = *(const float4*)(src + off);
    f[1] = *(const float4*)(src + off + 4);
    __half2 o1[4];
    o1[0] = __floats2half2_rn(f[0].x, f[0].y);
    o1[1] = __floats2half2_rn(f[0].z, f[0].w);
    o1[2] = __floats2half2_rn(f[1].x, f[1].y);
    o1[3] = __floats2half2_rn(f[1].z, f[1].w);
    *(uint4*)(h1 + off) = *(uint4*)o1;
}

__global__ void split_all(const float* __restrict__ hidden,
                          const float* __restrict__ wq,
                          const float* __restrict__ wk,
                          const float* __restrict__ wv,
                          const float* __restrict__ wo) {
    int g = (blockIdx.x * blockDim.x + threadIdx.x) * 8;
    if (g < SEG0)      split8_single(hidden, g_h1, g);
    else if (g < SEG1) split8_pair(wq, g_wq1, g_wq2, g - SEG0);
    else if (g < SEG2) split8_pair(wk, g_wk1, g_wk2, g - SEG1);
    else if (g < SEG3) split8_pair(wv, g_wv1, g_wv2, g - SEG2);
    else               split8_pair(wo, g_wo1, g_wo2, g - SEG3);
}

// ---------------------------------------------------------------------------
// warp-MMA primitives
// ---------------------------------------------------------------------------
__device__ __forceinline__ void ldsm_x4(uint32_t addr, uint32_t& r0, uint32_t& r1,
                                        uint32_t& r2, uint32_t& r3) {
    asm volatile("ldmatrix.sync.aligned.m8n8.x4.shared.b16 {%0,%1,%2,%3}, [%4];"
                 : "=r"(r0), "=r"(r1), "=r"(r2), "=r"(r3) : "r"(addr));
}

__device__ __forceinline__ void mma_f16(float* c, const uint32_t* a, const uint32_t* b) {
    asm volatile(
        "mma.sync.aligned.m16n8k16.row.col.f32.f16.f16.f32 "
        "{%0,%1,%2,%3},{%4,%5,%6,%7},{%8,%9},{%0,%1,%2,%3};"
        : "+f"(c[0]), "+f"(c[1]), "+f"(c[2]), "+f"(c[3])
        : "r"(a[0]), "r"(a[1]), "r"(a[2]), "r"(a[3]), "r"(b[0]), "r"(b[1]));
}

// ---------------------------------------------------------------------------
// fp16x2 GEMM body: C = A1·B1 + A1·B2. Block 256x128, warp 64x64, BK=64,
// 256 threads, 3-stage cp.async, 144B-padded rows.
// Epilogue modes: 0 = fp32, 1 = RoPE + fp16 single (Q), 2 = RoPE + fp16 pair (K).
// ---------------------------------------------------------------------------
#define GBK  64
#define LDT  144
#define A_T  (256 * LDT)
#define B_T  (128 * LDT)
#define STG  (A_T + 2 * B_T)             // 73728
#define GEMM_SMEM (3 * STG)              // 221184

__device__ __forceinline__ void gemm_body_f16(
    const __half* __restrict__ A1,
    const __half* __restrict__ B1, const __half* __restrict__ B2,
    float* __restrict__ Cf, __half* __restrict__ Ch1, __half* __restrict__ Ch2,
    const float* __restrict__ cosb, const float* __restrict__ sinb,
    int mode, int N, int bm, int bn, char* smem) {
    const int tid = threadIdx.x;
    const int lane = tid & 31;
    const int warp = tid >> 5;
    const int wr = warp >> 1;
    const int wc = warp & 1;
    uint32_t sbase = (uint32_t)__cvta_generic_to_shared(smem);

    float acc[4][8][4];
#pragma unroll
    for (int mi = 0; mi < 4; mi++)
#pragma unroll
        for (int ni = 0; ni < 8; ni++)
#pragma unroll
            for (int t = 0; t < 4; t++) acc[mi][ni][t] = 0.f;

    auto load_stage = [&](int s, int it) {
        const int kbase = it * GBK;
        uint32_t dst0 = sbase + s * STG;
#pragma unroll
        for (int i = 0; i < 16; i++) {
            int c = tid + i * 256;
            const __half* gsrc;
            uint32_t daddr;
            if (c < 2048) {
                int row = c >> 3;
                int ch = c & 7;
                gsrc = A1 + (size_t)(bm + row) * KDIM + kbase + ch * 8;
                daddr = dst0 + row * LDT + ch * 16;
            } else {
                int cb = c - 2048;
                int mat = cb >> 10;
                int idx = cb & 1023;
                int row = idx >> 3;
                int ch = idx & 7;
                gsrc = (mat ? B2 : B1) + (size_t)(bn + row) * KDIM + kbase + ch * 8;
                daddr = dst0 + A_T + mat * B_T + row * LDT + ch * 16;
            }
            asm volatile("cp.async.cg.shared.global [%0], [%1], 16;"
                         :: "r"(daddr), "l"(gsrc));
        }
        asm volatile("cp.async.commit_group;");
    };

    const int NIT = KDIM / GBK;
    load_stage(0, 0);
    load_stage(1, 1);

    const int brow = (lane & 7) + ((lane >> 4) << 3);
    const int bch = (lane >> 3) & 1;

    for (int it = 0; it < NIT; it++) {
        asm volatile("cp.async.wait_group 1;");
        __syncthreads();
        if (it + 2 < NIT) load_stage((it + 2) % 3, it + 2);
        else              asm volatile("cp.async.commit_group;");

        uint32_t sa = sbase + (it % 3) * STG;
#pragma unroll
        for (int ks = 0; ks < 4; ks++) {
            uint32_t af[4][4];
#pragma unroll
            for (int mi = 0; mi < 4; mi++) {
                uint32_t off = (uint32_t)((wr * 64 + mi * 16 + (lane & 15)) * LDT +
                                          ks * 32 + ((lane >> 4) & 1) * 16);
                ldsm_x4(sa + off, af[mi][0], af[mi][1], af[mi][2], af[mi][3]);
            }
#pragma unroll
            for (int half = 0; half < 2; half++) {
                uint32_t b1[4][2], b2[4][2];
#pragma unroll
                for (int np = 0; np < 2; np++) {
                    uint32_t off = (uint32_t)((wc * 64 + half * 32 + np * 16 + brow) * LDT +
                                              ks * 32 + bch * 16);
                    uint32_t r0, r1, r2, r3;
                    ldsm_x4(sa + A_T + off, r0, r1, r2, r3);
                    b1[np * 2][0] = r0; b1[np * 2][1] = r1;
                    b1[np * 2 + 1][0] = r2; b1[np * 2 + 1][1] = r3;
                    ldsm_x4(sa + A_T + B_T + off, r0, r1, r2, r3);
                    b2[np * 2][0] = r0; b2[np * 2][1] = r1;
                    b2[np * 2 + 1][0] = r2; b2[np * 2 + 1][1] = r3;
                }
#pragma unroll
                for (int mi = 0; mi < 4; mi++)
#pragma unroll
                    for (int nf = 0; nf < 4; nf++) {
                        float* a = acc[mi][half * 4 + nf];
                        mma_f16(a, af[mi], b1[nf]);
                        mma_f16(a, af[mi], b2[nf]);
                    }
            }
        }
    }

    if (mode == 0) {
#pragma unroll
        for (int mi = 0; mi < 4; mi++) {
            const int r0 = bm + wr * 64 + mi * 16 + (lane >> 2);
#pragma unroll
            for (int ni = 0; ni < 8; ni++) {
                const int col = bn + wc * 64 + ni * 8 + (lane & 3) * 2;
                *(float2*)&Cf[(size_t)r0 * N + col] = make_float2(acc[mi][ni][0], acc[mi][ni][1]);
                *(float2*)&Cf[(size_t)(r0 + 8) * N + col] = make_float2(acc[mi][ni][2], acc[mi][ni][3]);
            }
        }
    } else {
#pragma unroll
        for (int mi = 0; mi < 4; mi++) {
            const int r0 = bm + wr * 64 + mi * 16 + (lane >> 2);
            const int r1 = r0 + 8;
#pragma unroll
            for (int ni = 0; ni < 8; ni++) {
                const int col = bn + wc * 64 + ni * 8 + (lane & 3) * 2;
                const int i = (col & 127) >> 1;
                float c0 = cosb[r0 * 64 + i], s0 = sinb[r0 * 64 + i];
                float c1 = cosb[r1 * 64 + i], s1 = sinb[r1 * 64 + i];
                float a0 = acc[mi][ni][0], b0 = acc[mi][ni][1];
                float a1 = acc[mi][ni][2], b1 = acc[mi][ni][3];
                float x0 = a0 * c0 - b0 * s0, y0 = a0 * s0 + b0 * c0;
                float x1 = a1 * c1 - b1 * s1, y1 = a1 * s1 + b1 * c1;
                if (mode == 1) {
                    __half2 p0 = __floats2half2_rn(x0, y0);
                    __half2 p1 = __floats2half2_rn(x1, y1);
                    *(uint32_t*)&Ch1[(size_t)r0 * N + col] = *(uint32_t*)&p0;
                    *(uint32_t*)&Ch1[(size_t)r1 * N + col] = *(uint32_t*)&p1;
                } else {
                    uint32_t lo32, hi32;
                    hi32 = pack_hl_f16(x0, y0, lo32);
                    *(uint32_t*)&Ch1[(size_t)r0 * N + col] = hi32;
                    *(uint32_t*)&Ch2[(size_t)r0 * N + col] = lo32;
                    hi32 = pack_hl_f16(x1, y1, lo32);
                    *(uint32_t*)&Ch1[(size_t)r1 * N + col] = hi32;
                    *(uint32_t*)&Ch2[(size_t)r1 * N + col] = lo32;
                }
            }
        }
    }
}

__global__ __launch_bounds__(256, 1) void gemm_qkv(const float* __restrict__ cosb,
                                                   const float* __restrict__ sinb) {
    extern __shared__ char smem[];
    const int y = blockIdx.y;
    const int bm = blockIdx.x * 256;
    if (y < 32) {
        gemm_body_f16(g_h1, g_wq1, g_wq2, nullptr, g_q1, nullptr,
                      cosb, sinb, 1, HID, bm, y * 128, smem);
    } else if (y < 40) {
        gemm_body_f16(g_h1, g_wk1, g_wk2, nullptr, g_k1, g_k2,
                      cosb, sinb, 2, KVDIM, bm, (y - 32) * 128, smem);
    } else {
        gemm_body_f16(g_h1, g_wv1, g_wv2, g_v, nullptr, nullptr,
                      nullptr, nullptr, 0, KVDIM, bm, (y - 40) * 128, smem);
    }
}

__global__ __launch_bounds__(256, 1) void gemm_o(float* __restrict__ out) {
    extern __shared__ char smem[];
    gemm_body_f16(g_at1, g_wo1, g_wo2, out, nullptr, nullptr,
                  nullptr, nullptr, 0, HID, blockIdx.x * 256, blockIdx.y * 128, smem);
}

// ---------------------------------------------------------------------------
// transpose + split: v[S,1024] fp32 -> vT fp16 hi/lo [1024, S]
// ---------------------------------------------------------------------------
__global__ void transpose_split(const float* __restrict__ v,
                                __half* __restrict__ th,
                                __half* __restrict__ tl) {
    __shared__ float tile[32][33];
    const int bs = blockIdx.x * 32;
    const int bd = blockIdx.y * 32;
    const int tx = threadIdx.x;
    const int ty = threadIdx.y;
#pragma unroll
    for (int i = 0; i < 4; i++) {
        int sy = ty * 4 + i;
        tile[sy][tx] = v[(size_t)(bs + sy) * KVDIM + bd + tx];
    }
    __syncthreads();
#pragma unroll
    for (int i = 0; i < 4; i++) {
        int dy = ty * 4 + i;
        float val = tile[tx][dy];
        __half h = __float2half_rn(val);
        __half l = __float2half_rn(val - __half2float(h));
        th[(size_t)(bd + dy) * S_LEN + bs + tx] = h;
        tl[(size_t)(bd + dy) * S_LEN + bs + tx] = l;
    }
}

// ---------------------------------------------------------------------------
// Flash attention: QK fp16x2 (Q single in regs), PV fp16x2. BQ=64, 128 thr.
// K double-buffered / V pipelined. 2 CTA/SM. exp2 softmax. fp16 attn out.
// Grid (32 qb reversed, 32 h).
// ---------------------------------------------------------------------------
#define QLDT 272
#define VLDT 144
#define FK0  0
#define FK1  34816
#define FV   69632
#define FLASH_SMEM (FV + 36864)   // 106496

__global__ __launch_bounds__(128, 2) void flash_tc(
    const __half* __restrict__ q1,
    const __half* __restrict__ k1, const __half* __restrict__ k2,
    const __half* __restrict__ vt1, const __half* __restrict__ vt2,
    __half* __restrict__ o1) {
    extern __shared__ char sm[];
    const int qb = (int)gridDim.x - 1 - (int)blockIdx.x;
    const int h  = blockIdx.y;
    const int kvh = h >> 2;
    const int tid = threadIdx.x;
    const int lane = tid & 31;
    const int w = tid >> 5;
    const int q0 = qb * 64;
    const float scale2 = 0.12751744685137577f;   // (1/sqrt(128)) * log2(e)
    uint32_t sb = (uint32_t)__cvta_generic_to_shared(sm);

    const int brow = (lane & 7) + ((lane >> 4) << 3);
    const int bch = (lane >> 3) & 1;

    // stage Q (single) into FK1, then load fragments into registers
    for (int i = tid; i < 1024; i += 128) {
        int r = i >> 4;
        int c = i & 15;
        const __half* src = q1 + (size_t)(q0 + r) * HID + h * HD + c * 8;
        *(uint4*)(sm + FK1 + r * QLDT + c * 16) = *(const uint4*)src;
    }
    __syncthreads();
    uint32_t qf[8][4];
#pragma unroll
    for (int kf = 0; kf < 8; kf++) {
        uint32_t aoff = (uint32_t)((w * 16 + (lane & 15)) * QLDT + kf * 32 + (lane >> 4) * 16);
        ldsm_x4(sb + FK1 + aoff, qf[kf][0], qf[kf][1], qf[kf][2], qf[kf][3]);
    }
    __syncthreads();

    auto loadK = [&](int kb) {
        const int k0 = kb * 64;
        uint32_t kdst = sb + ((kb & 1) ? FK1 : FK0);
#pragma unroll
        for (int i0 = 0; i0 < 16; i0++) {
            int i = tid + i0 * 128;
            int mat = i >> 10;
            int idx = i & 1023;
            int r = idx >> 4;
            int c = idx & 15;
            const void* src = (mat ? k2 : k1) + (size_t)(k0 + r) * KVDIM + kvh * HD + c * 8;
            asm volatile("cp.async.cg.shared.global [%0], [%1], 16;"
                         :: "r"(kdst + mat * 17408 + r * QLDT + c * 16), "l"(src));
        }
        asm volatile("cp.async.commit_group;");
    };
    auto loadV = [&](int kb) {
        const int k0 = kb * 64;
        uint32_t vdst = sb + FV;
#pragma unroll
        for (int i0 = 0; i0 < 16; i0++) {
            int i = tid + i0 * 128;
            int mat = i >> 10;
            int idx = i & 1023;
            int r = idx >> 3;
            int c = idx & 7;
            const void* src = (mat ? vt2 : vt1) + (size_t)(kvh * HD + r) * S_LEN + k0 + c * 8;
            asm volatile("cp.async.cg.shared.global [%0], [%1], 16;"
                         :: "r"(vdst + mat * 18432 + r * VLDT + c * 16), "l"(src));
        }
        asm volatile("cp.async.commit_group;");
    };

    float m0 = -1e30f, m1 = -1e30f, l0 = 0.f, l1 = 0.f;
    float oa[16][4];
#pragma unroll
    for (int i = 0; i < 16; i++)
#pragma unroll
        for (int t = 0; t < 4; t++) oa[i][t] = 0.f;

    const int r0g = q0 + w * 16 + (lane >> 2);
    const int r1g = r0g + 8;

    loadK(0);

    for (int kb = 0; kb <= qb; kb++) {
        const int k0 = kb * 64;
        loadV(kb);
        if (kb < qb) loadK(kb + 1);
        else         asm volatile("cp.async.commit_group;");
        asm volatile("cp.async.wait_group 2;");
        __syncthreads();

        const uint32_t kbase = sb + ((kb & 1) ? FK1 : FK0);

        // S = Q K^T (Q single fp16, K hi+lo: 4 MMAs per np)
        float s[8][4];
#pragma unroll
        for (int nf = 0; nf < 8; nf++)
#pragma unroll
            for (int t = 0; t < 4; t++) s[nf][t] = 0.f;

#pragma unroll
        for (int kf = 0; kf < 8; kf++) {
#pragma unroll
            for (int np = 0; np < 4; np++) {
                uint32_t boff = (uint32_t)((np * 16 + brow) * QLDT + kf * 32 + bch * 16);
                uint32_t b1[4], b2[4];
                ldsm_x4(kbase + boff, b1[0], b1[1], b1[2], b1[3]);
                ldsm_x4(kbase + 17408 + boff, b2[0], b2[1], b2[2], b2[3]);
                mma_f16(s[np * 2], qf[kf], b1);
                mma_f16(s[np * 2], qf[kf], b2);
                mma_f16(s[np * 2 + 1], qf[kf], b1 + 2);
                mma_f16(s[np * 2 + 1], qf[kf], b2 + 2);
            }
        }

#pragma unroll
        for (int nf = 0; nf < 8; nf++)
#pragma unroll
            for (int t = 0; t < 4; t++) s[nf][t] *= scale2;
        if (kb == qb) {
#pragma unroll
            for (int nf = 0; nf < 8; nf++) {
                int cg = k0 + nf * 8 + (lane & 3) * 2;
                if (cg > r0g)     s[nf][0] = -1e30f;
                if (cg + 1 > r0g) s[nf][1] = -1e30f;
                if (cg > r1g)     s[nf][2] = -1e30f;
                if (cg + 1 > r1g) s[nf][3] = -1e30f;
            }
        }

        float mx0 = -1e30f, mx1 = -1e30f;
#pragma unroll
        for (int nf = 0; nf < 8; nf++) {
            mx0 = fmaxf(mx0, fmaxf(s[nf][0], s[nf][1]));
            mx1 = fmaxf(mx1, fmaxf(s[nf][2], s[nf][3]));
        }
        mx0 = fmaxf(mx0, __shfl_xor_sync(0xffffffffu, mx0, 1));
        mx0 = fmaxf(mx0, __shfl_xor_sync(0xffffffffu, mx0, 2));
        mx1 = fmaxf(mx1, __shfl_xor_sync(0xffffffffu, mx1, 1));
        mx1 = fmaxf(mx1, __shfl_xor_sync(0xffffffffu, mx1, 2));
        float mn0 = fmaxf(m0, mx0);
        float mn1 = fmaxf(m1, mx1);
        float c0 = exp2f(m0 - mn0);
        float c1 = exp2f(m1 - mn1);
        m0 = mn0; m1 = mn1;
        float rs0 = 0.f, rs1 = 0.f;
#pragma unroll
        for (int nf = 0; nf < 8; nf++) {
            s[nf][0] = exp2f(s[nf][0] - m0); rs0 += s[nf][0];
            s[nf][1] = exp2f(s[nf][1] - m0); rs0 += s[nf][1];
            s[nf][2] = exp2f(s[nf][2] - m1); rs1 += s[nf][2];
            s[nf][3] = exp2f(s[nf][3] - m1); rs1 += s[nf][3];
        }
        rs0 += __shfl_xor_sync(0xffffffffu, rs0, 1);
        rs0 += __shfl_xor_sync(0xffffffffu, rs0, 2);
        rs1 += __shfl_xor_sync(0xffffffffu, rs1, 1);
        rs1 += __shfl_xor_sync(0xffffffffu, rs1, 2);
        l0 = l0 * c0 + rs0;
        l1 = l1 * c1 + rs1;
#pragma unroll
        for (int i = 0; i < 16; i++) {
            oa[i][0] *= c0; oa[i][1] *= c0;
            oa[i][2] *= c1; oa[i][3] *= c1;
        }

        asm volatile("cp.async.wait_group 1;");
        __syncthreads();

        // O += P V (P single fp16, V hi+lo fp16: 4 MMAs per np)
#pragma unroll
        for (int kf2 = 0; kf2 < 4; kf2++) {
            uint32_t pah[4];
            {
                __half2 t0 = __floats2half2_rn(s[2 * kf2][0], s[2 * kf2][1]);
                __half2 t1 = __floats2half2_rn(s[2 * kf2][2], s[2 * kf2][3]);
                __half2 t2 = __floats2half2_rn(s[2 * kf2 + 1][0], s[2 * kf2 + 1][1]);
                __half2 t3 = __floats2half2_rn(s[2 * kf2 + 1][2], s[2 * kf2 + 1][3]);
                pah[0] = *(uint32_t*)&t0;
                pah[1] = *(uint32_t*)&t1;
                pah[2] = *(uint32_t*)&t2;
                pah[3] = *(uint32_t*)&t3;
            }
#pragma unroll
            for (int np = 0; np < 8; np++) {
                uint32_t voff = (uint32_t)((np * 16 + brow) * VLDT + kf2 * 32 + bch * 16);
                uint32_t v1[4], v2[4];
                ldsm_x4(sb + FV + voff, v1[0], v1[1], v1[2], v1[3]);
                ldsm_x4(sb + FV + 18432 + voff, v2[0], v2[1], v2[2], v2[3]);
                mma_f16(oa[np * 2], pah, v1);
                mma_f16(oa[np * 2], pah, v2);
                mma_f16(oa[np * 2 + 1], pah, v1 + 2);
                mma_f16(oa[np * 2 + 1], pah, v2 + 2);
            }
        }
        __syncthreads();
    }

    const float inv0 = 1.0f / l0;
    const float inv1 = 1.0f / l1;
#pragma unroll
    for (int nf2 = 0; nf2 < 16; nf2++) {
        int col = h * HD + nf2 * 8 + (lane & 3) * 2;
        __half2 p0 = __floats2half2_rn(oa[nf2][0] * inv0, oa[nf2][1] * inv0);
        __half2 p1 = __floats2half2_rn(oa[nf2][2] * inv1, oa[nf2][3] * inv1);
        *(uint32_t*)&o1[(size_t)r0g * HID + col] = *(uint32_t*)&p0;
        *(uint32_t*)&o1[(size_t)r1g * HID + col] = *(uint32_t*)&p1;
    }
}

// ---------------------------------------------------------------------------
// launcher
// ---------------------------------------------------------------------------
extern "C" void kernel_launch(void* const* d_in, const int* in_sizes, int n_in,
                              void* d_out, int out_size) {
    const float* hidden = (const float*)d_in[0];
    const float* cosb = (const float*)d_in[2];
    const float* sinb = (const float*)d_in[3];
    const float* wq = (const float*)d_in[4];
    const float* wk = (const float*)d_in[5];
    const float* wv = (const float*)d_in[6];
    const float* wo = (const float*)d_in[7];
    float* out = (float*)d_out;

    float* v;
    cudaGetSymbolAddress((void**)&v, g_v);
    __half *at1, *vt1, *vt2, *q1, *k1, *k2;
    cudaGetSymbolAddress((void**)&at1, g_at1);
    cudaGetSymbolAddress((void**)&vt1, g_vt1);
    cudaGetSymbolAddress((void**)&vt2, g_vt2);
    cudaGetSymbolAddress((void**)&q1, g_q1);
    cudaGetSymbolAddress((void**)&k1, g_k1);
    cudaGetSymbolAddress((void**)&k2, g_k2);

    split_all<<<SPLIT_GRID, 256>>>(hidden, wq, wk, wv, wo);

    cudaFuncSetAttribute(gemm_qkv, cudaFuncAttributeMaxDynamicSharedMemorySize,
                         GEMM_SMEM);
    cudaFuncSetAttribute(gemm_o, cudaFuncAttributeMaxDynamicSharedMemorySize,
                         GEMM_SMEM);

    gemm_qkv<<<dim3(S_LEN / 256, 48), 256, GEMM_SMEM>>>(cosb, sinb);

    transpose_split<<<dim3(S_LEN / 32, KVDIM / 32), dim3(32, 8)>>>(v, vt1, vt2);

    cudaFuncSetAttribute(flash_tc, cudaFuncAttributeMaxDynamicSharedMemorySize,
                         FLASH_SMEM);
    flash_tc<<<dim3(32, 32), 128, FLASH_SMEM>>>(q1, k1, k2, vt1, vt2, at1);

    gemm_o<<<dim3(S_LEN / 256, HID / 128), 256, GEMM_SMEM>>>(out);
}

// round 15
// speedup vs baseline: 4.4338x; 1.2124x over previous
#include <cuda_runtime.h>
#include <cuda_bf16.h>
#include <cuda_fp16.h>
#include <stdint.h>

// ---------------------------------------------------------------------------
// LlamaAttention: S=2048, HID=4096, NH=32, NKV=8, D=128
// Projections: fp16 warp-MMA GEMM. Q/K: B hi+lo (2 MMAs). V/O: B single.
// Flash: QK fp16x2 (Q single, K hi+lo), PV fp16 single x single.
// RoPE fused in QKV epilogue. HMMA-only path.
// ---------------------------------------------------------------------------

#define S_LEN 2048
#define HID   4096
#define NH    32
#define NKV   8
#define HD    128
#define KVDIM (NKV * HD)   // 1024
#define KDIM  4096

// fp16 GEMM operands
__device__ __half g_h1[S_LEN * KDIM];
__device__ __half g_wq1[HID * KDIM],   g_wq2[HID * KDIM];
__device__ __half g_wk1[KVDIM * KDIM], g_wk2[KVDIM * KDIM];
__device__ __half g_wv1[KVDIM * KDIM];
__device__ __half g_wo1[HID * KDIM];
__device__ __half g_at1[S_LEN * KDIM];

// attention operands
__device__ __half g_q1[S_LEN * HID];
__device__ __half g_k1[S_LEN * KVDIM];
__device__ __half g_k2[S_LEN * KVDIM];
__device__ __half g_v16[S_LEN * KVDIM];     // V (fp16, row-major)
__device__ __half g_vt1[KVDIM * S_LEN];     // V^T (fp16)

__device__ __forceinline__ uint32_t pack_hl_f16(float f0, float f1, uint32_t& lo) {
    __half2 h = __floats2half2_rn(f0, f1);
    float r0 = f0 - __half2float(h.x);
    float r1 = f1 - __half2float(h.y);
    __half2 l = __floats2half2_rn(r0, r1);
    lo = *(uint32_t*)&l;
    return *(uint32_t*)&h;
}

// ---------------------------------------------------------------------------
// fused split: hidden single; wq/wk pair; wv/wo single.
// ---------------------------------------------------------------------------
#define N_HID (S_LEN * KDIM)
#define N_WQ  (HID * KDIM)
#define N_WKV (KVDIM * KDIM)
#define SEG0  N_HID
#define SEG1  (SEG0 + N_WQ)
#define SEG2  (SEG1 + N_WKV)
#define SEG3  (SEG2 + N_WKV)
#define SEG4  (SEG3 + N_WQ)
#define SPLIT_GRID (SEG4 / (8 * 256))

__device__ __forceinline__ void split8_pair(const float* src, __half* h1,
                                            __half* h2, int off) {
    float4 f[2];
    f[0] = *(const float4*)(src + off);
    f[1] = *(const float4*)(src + off + 4);
    __half2 o1[4], o2[4];
#pragma unroll
    for (int j = 0; j < 2; j++) {
        const float v[4] = {f[j].x, f[j].y, f[j].z, f[j].w};
#pragma unroll
        for (int p = 0; p < 2; p++) {
            __half a = __float2half_rn(v[p * 2]);
            __half b = __float2half_rn(v[p * 2 + 1]);
            __half ra = __float2half_rn(v[p * 2] - __half2float(a));
            __half rb = __float2half_rn(v[p * 2 + 1] - __half2float(b));
            o1[j * 2 + p] = __halves2half2(a, b);
            o2[j * 2 + p] = __halves2half2(ra, rb);
        }
    }
    *(uint4*)(h1 + off) = *(uint4*)o1;
    *(uint4*)(h2 + off) = *(uint4*)o2;
}

__device__ __forceinline__ void split8_single(const float* src, __half* h1, int off) {
    float4 f[2];
    f[0] = *(const float4*)(src + off);
    f[1] = *(const float4*)(src + off + 4);
    __half2 o1[4];
    o1[0] = __floats2half2_rn(f[0].x, f[0].y);
    o1[1] = __floats2half2_rn(f[0].z, f[0].w);
    o1[2] = __floats2half2_rn(f[1].x, f[1].y);
    o1[3] = __floats2half2_rn(f[1].z, f[1].w);
    *(uint4*)(h1 + off) = *(uint4*)o1;
}

__global__ void split_all(const float* __restrict__ hidden,
                          const float* __restrict__ wq,
                          const float* __restrict__ wk,
                          const float* __restrict__ wv,
                          const float* __restrict__ wo) {
    int g = (blockIdx.x * blockDim.x + threadIdx.x) * 8;
    if (g < SEG0)      split8_single(hidden, g_h1, g);
    else if (g < SEG1) split8_pair(wq, g_wq1, g_wq2, g - SEG0);
    else if (g < SEG2) split8_pair(wk, g_wk1, g_wk2, g - SEG1);
    else if (g < SEG3) split8_single(wv, g_wv1, g - SEG2);
    else               split8_single(wo, g_wo1, g - SEG3);
}

// ---------------------------------------------------------------------------
// warp-MMA primitives
// ---------------------------------------------------------------------------
__device__ __forceinline__ void ldsm_x4(uint32_t addr, uint32_t& r0, uint32_t& r1,
                                        uint32_t& r2, uint32_t& r3) {
    asm volatile("ldmatrix.sync.aligned.m8n8.x4.shared.b16 {%0,%1,%2,%3}, [%4];"
                 : "=r"(r0), "=r"(r1), "=r"(r2), "=r"(r3) : "r"(addr));
}

__device__ __forceinline__ void mma_f16(float* c, const uint32_t* a, const uint32_t* b) {
    asm volatile(
        "mma.sync.aligned.m16n8k16.row.col.f32.f16.f16.f32 "
        "{%0,%1,%2,%3},{%4,%5,%6,%7},{%8,%9},{%0,%1,%2,%3};"
        : "+f"(c[0]), "+f"(c[1]), "+f"(c[2]), "+f"(c[3])
        : "r"(a[0]), "r"(a[1]), "r"(a[2]), "r"(a[3]), "r"(b[0]), "r"(b[1]));
}

// ---------------------------------------------------------------------------
// fp16 GEMM body: C = A1·B1 (+ A1·B2 if NB=2). Block 256x128, warp 64x64,
// BK=64, 256 threads, 3-stage cp.async, 144B-padded rows.
// MODE: 0 = fp32 out, 1 = RoPE + fp16 single, 2 = RoPE + fp16 pair,
//       3 = fp16 single out (no RoPE).
// ---------------------------------------------------------------------------
#define GBK  64
#define LDT  144
#define A_T  (256 * LDT)
#define B_T  (128 * LDT)
#define STG  (A_T + 2 * B_T)             // 73728 (uniform layout; NB=1 wastes B2 slot)
#define GEMM_SMEM (3 * STG)              // 221184

template <int NB, int MODE>
__device__ __forceinline__ void gemm_body_f16(
    const __half* __restrict__ A1,
    const __half* __restrict__ B1, const __half* __restrict__ B2,
    float* __restrict__ Cf, __half* __restrict__ Ch1, __half* __restrict__ Ch2,
    const float* __restrict__ cosb, const float* __restrict__ sinb,
    int N, int bm, int bn, char* smem) {
    const int tid = threadIdx.x;
    const int lane = tid & 31;
    const int warp = tid >> 5;
    const int wr = warp >> 1;
    const int wc = warp & 1;
    uint32_t sbase = (uint32_t)__cvta_generic_to_shared(smem);

    float acc[4][8][4];
#pragma unroll
    for (int mi = 0; mi < 4; mi++)
#pragma unroll
        for (int ni = 0; ni < 8; ni++)
#pragma unroll
            for (int t = 0; t < 4; t++) acc[mi][ni][t] = 0.f;

    auto load_stage = [&](int s, int it) {
        const int kbase = it * GBK;
        uint32_t dst0 = sbase + s * STG;
        const int NCH = (NB == 2) ? 16 : 12;   // 4096 or 3072 chunks / 256 thr
#pragma unroll
        for (int i = 0; i < NCH; i++) {
            int c = tid + i * 256;
            const __half* gsrc;
            uint32_t daddr;
            if (c < 2048) {
                int row = c >> 3;
                int ch = c & 7;
                gsrc = A1 + (size_t)(bm + row) * KDIM + kbase + ch * 8;
                daddr = dst0 + row * LDT + ch * 16;
            } else {
                int cb = c - 2048;
                int mat = cb >> 10;
                int idx = cb & 1023;
                int row = idx >> 3;
                int ch = idx & 7;
                gsrc = (mat ? B2 : B1) + (size_t)(bn + row) * KDIM + kbase + ch * 8;
                daddr = dst0 + A_T + mat * B_T + row * LDT + ch * 16;
            }
            asm volatile("cp.async.cg.shared.global [%0], [%1], 16;"
                         :: "r"(daddr), "l"(gsrc));
        }
        asm volatile("cp.async.commit_group;");
    };

    const int NIT = KDIM / GBK;
    load_stage(0, 0);
    load_stage(1, 1);

    const int brow = (lane & 7) + ((lane >> 4) << 3);
    const int bch = (lane >> 3) & 1;

    for (int it = 0; it < NIT; it++) {
        asm volatile("cp.async.wait_group 1;");
        __syncthreads();
        if (it + 2 < NIT) load_stage((it + 2) % 3, it + 2);
        else              asm volatile("cp.async.commit_group;");

        uint32_t sa = sbase + (it % 3) * STG;
#pragma unroll
        for (int ks = 0; ks < 4; ks++) {
            uint32_t af[4][4];
#pragma unroll
            for (int mi = 0; mi < 4; mi++) {
                uint32_t off = (uint32_t)((wr * 64 + mi * 16 + (lane & 15)) * LDT +
                                          ks * 32 + ((lane >> 4) & 1) * 16);
                ldsm_x4(sa + off, af[mi][0], af[mi][1], af[mi][2], af[mi][3]);
            }
#pragma unroll
            for (int half = 0; half < 2; half++) {
                uint32_t b1[4][2], b2[4][2];
#pragma unroll
                for (int np = 0; np < 2; np++) {
                    uint32_t off = (uint32_t)((wc * 64 + half * 32 + np * 16 + brow) * LDT +
                                              ks * 32 + bch * 16);
                    uint32_t r0, r1, r2, r3;
                    ldsm_x4(sa + A_T + off, r0, r1, r2, r3);
                    b1[np * 2][0] = r0; b1[np * 2][1] = r1;
                    b1[np * 2 + 1][0] = r2; b1[np * 2 + 1][1] = r3;
                    if (NB == 2) {
                        ldsm_x4(sa + A_T + B_T + off, r0, r1, r2, r3);
                        b2[np * 2][0] = r0; b2[np * 2][1] = r1;
                        b2[np * 2 + 1][0] = r2; b2[np * 2 + 1][1] = r3;
                    }
                }
#pragma unroll
                for (int mi = 0; mi < 4; mi++)
#pragma unroll
                    for (int nf = 0; nf < 4; nf++) {
                        float* a = acc[mi][half * 4 + nf];
                        mma_f16(a, af[mi], b1[nf]);
                        if (NB == 2) mma_f16(a, af[mi], b2[nf]);
                    }
            }
        }
    }

    if (MODE == 0) {
#pragma unroll
        for (int mi = 0; mi < 4; mi++) {
            const int r0 = bm + wr * 64 + mi * 16 + (lane >> 2);
#pragma unroll
            for (int ni = 0; ni < 8; ni++) {
                const int col = bn + wc * 64 + ni * 8 + (lane & 3) * 2;
                *(float2*)&Cf[(size_t)r0 * N + col] = make_float2(acc[mi][ni][0], acc[mi][ni][1]);
                *(float2*)&Cf[(size_t)(r0 + 8) * N + col] = make_float2(acc[mi][ni][2], acc[mi][ni][3]);
            }
        }
    } else if (MODE == 3) {
#pragma unroll
        for (int mi = 0; mi < 4; mi++) {
            const int r0 = bm + wr * 64 + mi * 16 + (lane >> 2);
#pragma unroll
            for (int ni = 0; ni < 8; ni++) {
                const int col = bn + wc * 64 + ni * 8 + (lane & 3) * 2;
                __half2 p0 = __floats2half2_rn(acc[mi][ni][0], acc[mi][ni][1]);
                __half2 p1 = __floats2half2_rn(acc[mi][ni][2], acc[mi][ni][3]);
                *(uint32_t*)&Ch1[(size_t)r0 * N + col] = *(uint32_t*)&p0;
                *(uint32_t*)&Ch1[(size_t)(r0 + 8) * N + col] = *(uint32_t*)&p1;
            }
        }
    } else {
#pragma unroll
        for (int mi = 0; mi < 4; mi++) {
            const int r0 = bm + wr * 64 + mi * 16 + (lane >> 2);
            const int r1 = r0 + 8;
#pragma unroll
            for (int ni = 0; ni < 8; ni++) {
                const int col = bn + wc * 64 + ni * 8 + (lane & 3) * 2;
                const int i = (col & 127) >> 1;
                float c0 = cosb[r0 * 64 + i], s0 = sinb[r0 * 64 + i];
                float c1 = cosb[r1 * 64 + i], s1 = sinb[r1 * 64 + i];
                float a0 = acc[mi][ni][0], b0 = acc[mi][ni][1];
                float a1 = acc[mi][ni][2], b1 = acc[mi][ni][3];
                float x0 = a0 * c0 - b0 * s0, y0 = a0 * s0 + b0 * c0;
                float x1 = a1 * c1 - b1 * s1, y1 = a1 * s1 + b1 * c1;
                if (MODE == 1) {
                    __half2 p0 = __floats2half2_rn(x0, y0);
                    __half2 p1 = __floats2half2_rn(x1, y1);
                    *(uint32_t*)&Ch1[(size_t)r0 * N + col] = *(uint32_t*)&p0;
                    *(uint32_t*)&Ch1[(size_t)r1 * N + col] = *(uint32_t*)&p1;
                } else {
                    uint32_t lo32, hi32;
                    hi32 = pack_hl_f16(x0, y0, lo32);
                    *(uint32_t*)&Ch1[(size_t)r0 * N + col] = hi32;
                    *(uint32_t*)&Ch2[(size_t)r0 * N + col] = lo32;
                    hi32 = pack_hl_f16(x1, y1, lo32);
                    *(uint32_t*)&Ch1[(size_t)r1 * N + col] = hi32;
                    *(uint32_t*)&Ch2[(size_t)r1 * N + col] = lo32;
                }
            }
        }
    }
}

__global__ __launch_bounds__(256, 1) void gemm_qkv(const float* __restrict__ cosb,
                                                   const float* __restrict__ sinb) {
    extern __shared__ char smem[];
    const int y = blockIdx.y;
    const int bm = blockIdx.x * 256;
    if (y < 32) {
        gemm_body_f16<2, 1>(g_h1, g_wq1, g_wq2, nullptr, g_q1, nullptr,
                            cosb, sinb, HID, bm, y * 128, smem);
    } else if (y < 40) {
        gemm_body_f16<2, 2>(g_h1, g_wk1, g_wk2, nullptr, g_k1, g_k2,
                            cosb, sinb, KVDIM, bm, (y - 32) * 128, smem);
    } else {
        gemm_body_f16<1, 3>(g_h1, g_wv1, nullptr, nullptr, g_v16, nullptr,
                            nullptr, nullptr, KVDIM, bm, (y - 40) * 128, smem);
    }
}

__global__ __launch_bounds__(256, 1) void gemm_o(float* __restrict__ out) {
    extern __shared__ char smem[];
    gemm_body_f16<1, 0>(g_at1, g_wo1, nullptr, out, nullptr, nullptr,
                        nullptr, nullptr, HID, blockIdx.x * 256, blockIdx.y * 128, smem);
}

// ---------------------------------------------------------------------------
// transpose: v16[S,1024] fp16 -> vt1[1024, S] fp16
// ---------------------------------------------------------------------------
__global__ void transpose_v(const __half* __restrict__ v,
                            __half* __restrict__ th) {
    __shared__ __half tile[32][34];
    const int bs = blockIdx.x * 32;
    const int bd = blockIdx.y * 32;
    const int tx = threadIdx.x;
    const int ty = threadIdx.y;
#pragma unroll
    for (int i = 0; i < 4; i++) {
        int sy = ty * 4 + i;
        tile[sy][tx] = v[(size_t)(bs + sy) * KVDIM + bd + tx];
    }
    __syncthreads();
#pragma unroll
    for (int i = 0; i < 4; i++) {
        int dy = ty * 4 + i;
        th[(size_t)(bd + dy) * S_LEN + bs + tx] = tile[tx][dy];
    }
}

// ---------------------------------------------------------------------------
// Flash attention: QK fp16x2 (Q single in regs, K hi+lo), PV single x single.
// BQ=64, 128 thr, K double-buffered / V pipelined. 88KB -> 2 CTA/SM.
// exp2 softmax. fp16 attn out. Grid (32 qb reversed, 32 h).
// ---------------------------------------------------------------------------
#define QLDT 272
#define VLDT 144
#define FK0  0
#define FK1  34816
#define FV   69632
#define FLASH_SMEM (FV + 18432)   // 88064

__global__ __launch_bounds__(128, 2) void flash_tc(
    const __half* __restrict__ q1,
    const __half* __restrict__ k1, const __half* __restrict__ k2,
    const __half* __restrict__ vt1,
    __half* __restrict__ o1) {
    extern __shared__ char sm[];
    const int qb = (int)gridDim.x - 1 - (int)blockIdx.x;
    const int h  = blockIdx.y;
    const int kvh = h >> 2;
    const int tid = threadIdx.x;
    const int lane = tid & 31;
    const int w = tid >> 5;
    const int q0 = qb * 64;
    const float scale2 = 0.12751744685137577f;   // (1/sqrt(128)) * log2(e)
    uint32_t sb = (uint32_t)__cvta_generic_to_shared(sm);

    const int brow = (lane & 7) + ((lane >> 4) << 3);
    const int bch = (lane >> 3) & 1;

    // stage Q (single) into FK1, then load fragments into registers
    for (int i = tid; i < 1024; i += 128) {
        int r = i >> 4;
        int c = i & 15;
        const __half* src = q1 + (size_t)(q0 + r) * HID + h * HD + c * 8;
        *(uint4*)(sm + FK1 + r * QLDT + c * 16) = *(const uint4*)src;
    }
    __syncthreads();
    uint32_t qf[8][4];
#pragma unroll
    for (int kf = 0; kf < 8; kf++) {
        uint32_t aoff = (uint32_t)((w * 16 + (lane & 15)) * QLDT + kf * 32 + (lane >> 4) * 16);
        ldsm_x4(sb + FK1 + aoff, qf[kf][0], qf[kf][1], qf[kf][2], qf[kf][3]);
    }
    __syncthreads();

    auto loadK = [&](int kb) {
        const int k0 = kb * 64;
        uint32_t kdst = sb + ((kb & 1) ? FK1 : FK0);
#pragma unroll
        for (int i0 = 0; i0 < 16; i0++) {
            int i = tid + i0 * 128;
            int mat = i >> 10;
            int idx = i & 1023;
            int r = idx >> 4;
            int c = idx & 15;
            const void* src = (mat ? k2 : k1) + (size_t)(k0 + r) * KVDIM + kvh * HD + c * 8;
            asm volatile("cp.async.cg.shared.global [%0], [%1], 16;"
                         :: "r"(kdst + mat * 17408 + r * QLDT + c * 16), "l"(src));
        }
        asm volatile("cp.async.commit_group;");
    };
    auto loadV = [&](int kb) {
        const int k0 = kb * 64;
        uint32_t vdst = sb + FV;
#pragma unroll
        for (int i0 = 0; i0 < 8; i0++) {
            int i = tid + i0 * 128;
            int r = i >> 3;
            int c = i & 7;
            const void* src = vt1 + (size_t)(kvh * HD + r) * S_LEN + k0 + c * 8;
            asm volatile("cp.async.cg.shared.global [%0], [%1], 16;"
                         :: "r"(vdst + r * VLDT + c * 16), "l"(src));
        }
        asm volatile("cp.async.commit_group;");
    };

    float m0 = -1e30f, m1 = -1e30f, l0 = 0.f, l1 = 0.f;
    float oa[16][4];
#pragma unroll
    for (int i = 0; i < 16; i++)
#pragma unroll
        for (int t = 0; t < 4; t++) oa[i][t] = 0.f;

    const int r0g = q0 + w * 16 + (lane >> 2);
    const int r1g = r0g + 8;

    loadK(0);

    for (int kb = 0; kb <= qb; kb++) {
        const int k0 = kb * 64;
        loadV(kb);
        if (kb < qb) loadK(kb + 1);
        else         asm volatile("cp.async.commit_group;");
        asm volatile("cp.async.wait_group 2;");
        __syncthreads();

        const uint32_t kbase = sb + ((kb & 1) ? FK1 : FK0);

        float s[8][4];
#pragma unroll
        for (int nf = 0; nf < 8; nf++)
#pragma unroll
            for (int t = 0; t < 4; t++) s[nf][t] = 0.f;

#pragma unroll
        for (int kf = 0; kf < 8; kf++) {
#pragma unroll
            for (int np = 0; np < 4; np++) {
                uint32_t boff = (uint32_t)((np * 16 + brow) * QLDT + kf * 32 + bch * 16);
                uint32_t b1[4], b2[4];
                ldsm_x4(kbase + boff, b1[0], b1[1], b1[2], b1[3]);
                ldsm_x4(kbase + 17408 + boff, b2[0], b2[1], b2[2], b2[3]);
                mma_f16(s[np * 2], qf[kf], b1);
                mma_f16(s[np * 2], qf[kf], b2);
                mma_f16(s[np * 2 + 1], qf[kf], b1 + 2);
                mma_f16(s[np * 2 + 1], qf[kf], b2 + 2);
            }
        }

#pragma unroll
        for (int nf = 0; nf < 8; nf++)
#pragma unroll
            for (int t = 0; t < 4; t++) s[nf][t] *= scale2;
        if (kb == qb) {
#pragma unroll
            for (int nf = 0; nf < 8; nf++) {
                int cg = k0 + nf * 8 + (lane & 3) * 2;
                if (cg > r0g)     s[nf][0] = -1e30f;
                if (cg + 1 > r0g) s[nf][1] = -1e30f;
                if (cg > r1g)     s[nf][2] = -1e30f;
                if (cg + 1 > r1g) s[nf][3] = -1e30f;
            }
        }

        float mx0 = -1e30f, mx1 = -1e30f;
#pragma unroll
        for (int nf = 0; nf < 8; nf++) {
            mx0 = fmaxf(mx0, fmaxf(s[nf][0], s[nf][1]));
            mx1 = fmaxf(mx1, fmaxf(s[nf][2], s[nf][3]));
        }
        mx0 = fmaxf(mx0, __shfl_xor_sync(0xffffffffu, mx0, 1));
        mx0 = fmaxf(mx0, __shfl_xor_sync(0xffffffffu, mx0, 2));
        mx1 = fmaxf(mx1, __shfl_xor_sync(0xffffffffu, mx1, 1));
        mx1 = fmaxf(mx1, __shfl_xor_sync(0xffffffffu, mx1, 2));
        float mn0 = fmaxf(m0, mx0);
        float mn1 = fmaxf(m1, mx1);
        float c0 = exp2f(m0 - mn0);
        float c1 = exp2f(m1 - mn1);
        m0 = mn0; m1 = mn1;
        float rs0 = 0.f, rs1 = 0.f;
#pragma unroll
        for (int nf = 0; nf < 8; nf++) {
            s[nf][0] = exp2f(s[nf][0] - m0); rs0 += s[nf][0];
            s[nf][1] = exp2f(s[nf][1] - m0); rs0 += s[nf][1];
            s[nf][2] = exp2f(s[nf][2] - m1); rs1 += s[nf][2];
            s[nf][3] = exp2f(s[nf][3] - m1); rs1 += s[nf][3];
        }
        rs0 += __shfl_xor_sync(0xffffffffu, rs0, 1);
        rs0 += __shfl_xor_sync(0xffffffffu, rs0, 2);
        rs1 += __shfl_xor_sync(0xffffffffu, rs1, 1);
        rs1 += __shfl_xor_sync(0xffffffffu, rs1, 2);
        l0 = l0 * c0 + rs0;
        l1 = l1 * c1 + rs1;
#pragma unroll
        for (int i = 0; i < 16; i++) {
            oa[i][0] *= c0; oa[i][1] *= c0;
            oa[i][2] *= c1; oa[i][3] *= c1;
        }

        asm volatile("cp.async.wait_group 1;");
        __syncthreads();

        // O += P V (both single fp16: 2 MMAs per np)
#pragma unroll
        for (int kf2 = 0; kf2 < 4; kf2++) {
            uint32_t pah[4];
            {
                __half2 t0 = __floats2half2_rn(s[2 * kf2][0], s[2 * kf2][1]);
                __half2 t1 = __floats2half2_rn(s[2 * kf2][2], s[2 * kf2][3]);
                __half2 t2 = __floats2half2_rn(s[2 * kf2 + 1][0], s[2 * kf2 + 1][1]);
                __half2 t3 = __floats2half2_rn(s[2 * kf2 + 1][2], s[2 * kf2 + 1][3]);
                pah[0] = *(uint32_t*)&t0;
                pah[1] = *(uint32_t*)&t1;
                pah[2] = *(uint32_t*)&t2;
                pah[3] = *(uint32_t*)&t3;
            }
#pragma unroll
            for (int np = 0; np < 8; np++) {
                uint32_t voff = (uint32_t)((np * 16 + brow) * VLDT + kf2 * 32 + bch * 16);
                uint32_t v1[4];
                ldsm_x4(sb + FV + voff, v1[0], v1[1], v1[2], v1[3]);
                mma_f16(oa[np * 2], pah, v1);
                mma_f16(oa[np * 2 + 1], pah, v1 + 2);
            }
        }
        __syncthreads();
    }

    const float inv0 = 1.0f / l0;
    const float inv1 = 1.0f / l1;
#pragma unroll
    for (int nf2 = 0; nf2 < 16; nf2++) {
        int col = h * HD + nf2 * 8 + (lane & 3) * 2;
        __half2 p0 = __floats2half2_rn(oa[nf2][0] * inv0, oa[nf2][1] * inv0);
        __half2 p1 = __floats2half2_rn(oa[nf2][2] * inv1, oa[nf2][3] * inv1);
        *(uint32_t*)&o1[(size_t)r0g * HID + col] = *(uint32_t*)&p0;
        *(uint32_t*)&o1[(size_t)r1g * HID + col] = *(uint32_t*)&p1;
    }
}

// ---------------------------------------------------------------------------
// launcher
// ---------------------------------------------------------------------------
extern "C" void kernel_launch(void* const* d_in, const int* in_sizes, int n_in,
                              void* d_out, int out_size) {
    const float* hidden = (const float*)d_in[0];
    const float* cosb = (const float*)d_in[2];
    const float* sinb = (const float*)d_in[3];
    const float* wq = (const float*)d_in[4];
    const float* wk = (const float*)d_in[5];
    const float* wv = (const float*)d_in[6];
    const float* wo = (const float*)d_in[7];
    float* out = (float*)d_out;

    __half *at1, *vt1, *q1, *k1, *k2, *v16;
    cudaGetSymbolAddress((void**)&at1, g_at1);
    cudaGetSymbolAddress((void**)&vt1, g_vt1);
    cudaGetSymbolAddress((void**)&q1, g_q1);
    cudaGetSymbolAddress((void**)&k1, g_k1);
    cudaGetSymbolAddress((void**)&k2, g_k2);
    cudaGetSymbolAddress((void**)&v16, g_v16);

    split_all<<<SPLIT_GRID, 256>>>(hidden, wq, wk, wv, wo);

    cudaFuncSetAttribute(gemm_qkv, cudaFuncAttributeMaxDynamicSharedMemorySize,
                         GEMM_SMEM);
    cudaFuncSetAttribute(gemm_o, cudaFuncAttributeMaxDynamicSharedMemorySize,
                         GEMM_SMEM);

    gemm_qkv<<<dim3(S_LEN / 256, 48), 256, GEMM_SMEM>>>(cosb, sinb);

    transpose_v<<<dim3(S_LEN / 32, KVDIM / 32), dim3(32, 8)>>>(v16, vt1);

    cudaFuncSetAttribute(flash_tc, cudaFuncAttributeMaxDynamicSharedMemorySize,
                         FLASH_SMEM);
    flash_tc<<<dim3(32, 32), 128, FLASH_SMEM>>>(q1, k1, k2, vt1, at1);

    gemm_o<<<dim3(S_LEN / 256, HID / 128), 256, GEMM_SMEM>>>(out);
}